// round 1
// baseline (speedup 1.0000x reference)
#include <cuda_runtime.h>
#include <cuda_bf16.h>
#include <math.h>

// Problem constants
#define BATCH 2
#define SEQ   2048
#define EMB   1024
#define NHEAD 16
#define HDIM  64
#define MROWS (BATCH*SEQ)   // 4096

// ---------------------------------------------------------------------------
// Scratch (device globals; no runtime allocation allowed)
// ---------------------------------------------------------------------------
__device__ float g_Q[MROWS * EMB];
__device__ float g_K[MROWS * EMB];
__device__ float g_V[MROWS * EMB];
__device__ float g_A[MROWS * EMB];

// ---------------------------------------------------------------------------
// SGEMM: C[M,N] = A[M,K] @ W[N,K]^T + bias[N]   (torch Linear)
// BM=BN=128, BK=16, 256 threads, 8x8 per-thread microtile
// ---------------------------------------------------------------------------
#define BM 128
#define BN 128
#define BKK 16
#define TM 8
#define TN 8

__global__ __launch_bounds__(256) void sgemm_nt_bias(
    const float* __restrict__ A,     // [M,K]
    const float* __restrict__ W,     // [N,K]
    const float* __restrict__ bias,  // [N]
    float* __restrict__ C,           // [M,N]
    int M, int N, int K)
{
    __shared__ float As[BKK][BM + 4];
    __shared__ float Ws[BKK][BN + 4];

    const int tid = threadIdx.x;
    const int ty  = tid >> 4;        // 0..15 -> M microtile group
    const int tx  = tid & 15;        // 0..15 -> N microtile group
    const int bm  = blockIdx.y * BM;
    const int bn  = blockIdx.x * BN;

    const int lr = tid >> 2;         // 0..63 (load row)
    const int lc = (tid & 3) * 4;    // 0,4,8,12 (load col within BK)

    float acc[TM][TN];
#pragma unroll
    for (int i = 0; i < TM; i++)
#pragma unroll
        for (int j = 0; j < TN; j++) acc[i][j] = 0.f;

    for (int k0 = 0; k0 < K; k0 += BKK) {
#pragma unroll
        for (int i = 0; i < 2; i++) {
            int r = lr + i * 64;
            float4 v = *(const float4*)(A + (size_t)(bm + r) * K + k0 + lc);
            As[lc + 0][r] = v.x; As[lc + 1][r] = v.y;
            As[lc + 2][r] = v.z; As[lc + 3][r] = v.w;
        }
#pragma unroll
        for (int i = 0; i < 2; i++) {
            int r = lr + i * 64;
            float4 v = *(const float4*)(W + (size_t)(bn + r) * K + k0 + lc);
            Ws[lc + 0][r] = v.x; Ws[lc + 1][r] = v.y;
            Ws[lc + 2][r] = v.z; Ws[lc + 3][r] = v.w;
        }
        __syncthreads();

#pragma unroll
        for (int k = 0; k < BKK; k++) {
            float a[TM], b[TN];
            float4 a0 = *(const float4*)&As[k][ty * TM];
            float4 a1 = *(const float4*)&As[k][ty * TM + 4];
            a[0]=a0.x; a[1]=a0.y; a[2]=a0.z; a[3]=a0.w;
            a[4]=a1.x; a[5]=a1.y; a[6]=a1.z; a[7]=a1.w;
            float4 b0 = *(const float4*)&Ws[k][tx * TN];
            float4 b1 = *(const float4*)&Ws[k][tx * TN + 4];
            b[0]=b0.x; b[1]=b0.y; b[2]=b0.z; b[3]=b0.w;
            b[4]=b1.x; b[5]=b1.y; b[6]=b1.z; b[7]=b1.w;
#pragma unroll
            for (int i = 0; i < TM; i++)
#pragma unroll
                for (int j = 0; j < TN; j++)
                    acc[i][j] = fmaf(a[i], b[j], acc[i][j]);
        }
        __syncthreads();
    }

#pragma unroll
    for (int i = 0; i < TM; i++) {
        int r = bm + ty * TM + i;
#pragma unroll
        for (int j = 0; j < TN; j += 4) {
            int c = bn + tx * TN + j;
            float4 v;
            v.x = acc[i][j + 0] + bias[c + 0];
            v.y = acc[i][j + 1] + bias[c + 1];
            v.z = acc[i][j + 2] + bias[c + 2];
            v.w = acc[i][j + 3] + bias[c + 3];
            *(float4*)(C + (size_t)r * N + c) = v;
        }
    }
}

// ---------------------------------------------------------------------------
// Flash attention: per (b, h, q-tile of 64). Online softmax over Sk=2048 in
// 64-key tiles. Q/K stored transposed [d][q] in smem for float4 microtile
// loads; P staged transposed [k][q] for float4 PV loads.
// Layouts: Q/K/V/A are [B*S, EMB] row-major; head h occupies cols h*64..h*64+63.
// ---------------------------------------------------------------------------
#define BQ 64
#define BKV 64
#define SM_PAD 4
#define SROW (BQ + SM_PAD)   // 68

struct AttnSmem {
    float Qs[HDIM][SROW];   // [d][q]
    float Ks[HDIM][SROW];   // [d][k]
    float Vs[BKV][HDIM + SM_PAD]; // [k][d]
    float Ps[BKV][SROW];    // [k][q]
};

__global__ __launch_bounds__(256) void flash_attn_kernel()
{
    extern __shared__ char smem_raw[];
    AttnSmem* sm = reinterpret_cast<AttnSmem*>(smem_raw);

    const int qt = blockIdx.x;   // 0..31
    const int h  = blockIdx.y;   // 0..15
    const int b  = blockIdx.z;   // 0..1

    const float* Qb = g_Q + (size_t)b * SEQ * EMB + h * HDIM;
    const float* Kb = g_K + (size_t)b * SEQ * EMB + h * HDIM;
    const float* Vb = g_V + (size_t)b * SEQ * EMB + h * HDIM;
    float*       Ob = g_A + (size_t)b * SEQ * EMB + h * HDIM;

    const int tid = threadIdx.x;
    const int ty = tid >> 4;   // q-row group (0..15)
    const int tx = tid & 15;   // col group   (0..15)

    // Load Q tile (64 q x 64 d), store transposed [d][q]
#pragma unroll
    for (int it = 0; it < 4; it++) {
        int idx = tid + it * 256;       // 0..1023
        int q   = idx >> 4;             // 0..63
        int dc  = (idx & 15) * 4;       // 0..60
        float4 v = *(const float4*)(Qb + (size_t)(qt * BQ + q) * EMB + dc);
        sm->Qs[dc + 0][q] = v.x; sm->Qs[dc + 1][q] = v.y;
        sm->Qs[dc + 2][q] = v.z; sm->Qs[dc + 3][q] = v.w;
    }

    float mrow[4], lrow[4], acc[4][4];
#pragma unroll
    for (int i = 0; i < 4; i++) {
        mrow[i] = -1e30f; lrow[i] = 0.f;
#pragma unroll
        for (int j = 0; j < 4; j++) acc[i][j] = 0.f;
    }

    const float scale = 0.125f;  // 1/sqrt(64)

    for (int kt = 0; kt < SEQ / BKV; kt++) {
        __syncthreads();  // prior PV reads of Vs/Ps complete before overwrite
        // Load K tile transposed [d][k] and V tile natural [k][d]
#pragma unroll
        for (int it = 0; it < 4; it++) {
            int idx = tid + it * 256;
            int kk  = idx >> 4;
            int dc  = (idx & 15) * 4;
            float4 v = *(const float4*)(Kb + (size_t)(kt * BKV + kk) * EMB + dc);
            sm->Ks[dc + 0][kk] = v.x; sm->Ks[dc + 1][kk] = v.y;
            sm->Ks[dc + 2][kk] = v.z; sm->Ks[dc + 3][kk] = v.w;
            float4 w = *(const float4*)(Vb + (size_t)(kt * BKV + kk) * EMB + dc);
            *(float4*)&sm->Vs[kk][dc] = w;
        }
        __syncthreads();

        // S = Q K^T (thread tile: 4 q-rows x 4 k-cols)
        float s[4][4];
#pragma unroll
        for (int i = 0; i < 4; i++)
#pragma unroll
            for (int j = 0; j < 4; j++) s[i][j] = 0.f;

#pragma unroll
        for (int d = 0; d < HDIM; d++) {
            float4 aq = *(const float4*)&sm->Qs[d][ty * 4];
            float4 bk = *(const float4*)&sm->Ks[d][tx * 4];
            float a[4] = {aq.x, aq.y, aq.z, aq.w};
            float bb[4] = {bk.x, bk.y, bk.z, bk.w};
#pragma unroll
            for (int i = 0; i < 4; i++)
#pragma unroll
                for (int j = 0; j < 4; j++)
                    s[i][j] = fmaf(a[i], bb[j], s[i][j]);
        }
#pragma unroll
        for (int i = 0; i < 4; i++)
#pragma unroll
            for (int j = 0; j < 4; j++) s[i][j] *= scale;

        // Online softmax: row max/sum reduced across the 16 tx lanes
        float p[4][4];
#pragma unroll
        for (int i = 0; i < 4; i++) {
            float rm = fmaxf(fmaxf(s[i][0], s[i][1]), fmaxf(s[i][2], s[i][3]));
#pragma unroll
            for (int o = 8; o >= 1; o >>= 1)
                rm = fmaxf(rm, __shfl_xor_sync(0xffffffffu, rm, o));
            float mnew = fmaxf(mrow[i], rm);
            float corr = __expf(mrow[i] - mnew);
            float rs = 0.f;
#pragma unroll
            for (int j = 0; j < 4; j++) {
                p[i][j] = __expf(s[i][j] - mnew);
                rs += p[i][j];
            }
#pragma unroll
            for (int o = 8; o >= 1; o >>= 1)
                rs += __shfl_xor_sync(0xffffffffu, rs, o);
            lrow[i] = lrow[i] * corr + rs;
            mrow[i] = mnew;
#pragma unroll
            for (int j = 0; j < 4; j++) acc[i][j] *= corr;
        }

        // Stage P transposed [k][q]
#pragma unroll
        for (int i = 0; i < 4; i++)
#pragma unroll
            for (int j = 0; j < 4; j++)
                sm->Ps[tx * 4 + j][ty * 4 + i] = p[i][j];
        __syncthreads();

        // O += P V  (thread tile: 4 q x 4 hd; hd group = tx)
#pragma unroll
        for (int k = 0; k < BKV; k++) {
            float4 pq = *(const float4*)&sm->Ps[k][ty * 4];
            float4 vv = *(const float4*)&sm->Vs[k][tx * 4];
            float pp[4] = {pq.x, pq.y, pq.z, pq.w};
            float vvv[4] = {vv.x, vv.y, vv.z, vv.w};
#pragma unroll
            for (int i = 0; i < 4; i++)
#pragma unroll
                for (int j = 0; j < 4; j++)
                    acc[i][j] = fmaf(pp[i], vvv[j], acc[i][j]);
        }
    }

    // Normalize and write out: row qt*64+ty*4+i, col h*64 + tx*4+j
#pragma unroll
    for (int i = 0; i < 4; i++) {
        float inv = 1.0f / lrow[i];
        float4 v;
        v.x = acc[i][0] * inv; v.y = acc[i][1] * inv;
        v.z = acc[i][2] * inv; v.w = acc[i][3] * inv;
        *(float4*)(Ob + (size_t)(qt * BQ + ty * 4 + i) * EMB + tx * 4) = v;
    }
}

// ---------------------------------------------------------------------------
// Launch
// ---------------------------------------------------------------------------
extern "C" void kernel_launch(void* const* d_in, const int* in_sizes, int n_in,
                              void* d_out, int out_size)
{
    const float* query = (const float*)d_in[0];
    const float* key   = (const float*)d_in[1];
    const float* value = (const float*)d_in[2];
    const float* Wq    = (const float*)d_in[3];
    const float* bq    = (const float*)d_in[4];
    const float* Wk    = (const float*)d_in[5];
    const float* bk    = (const float*)d_in[6];
    const float* Wv    = (const float*)d_in[7];
    const float* bv    = (const float*)d_in[8];
    const float* Wo    = (const float*)d_in[9];
    const float* bo    = (const float*)d_in[10];
    float* out = (float*)d_out;

    float *pQ, *pK, *pV, *pA;
    cudaGetSymbolAddress((void**)&pQ, g_Q);
    cudaGetSymbolAddress((void**)&pK, g_K);
    cudaGetSymbolAddress((void**)&pV, g_V);
    cudaGetSymbolAddress((void**)&pA, g_A);

    static_assert(sizeof(AttnSmem) <= 96 * 1024, "smem");
    cudaFuncSetAttribute(flash_attn_kernel,
                         cudaFuncAttributeMaxDynamicSharedMemorySize,
                         (int)sizeof(AttnSmem));

    dim3 gblk(EMB / BN, MROWS / BM);   // (8, 32)

    sgemm_nt_bias<<<gblk, 256>>>(query, Wq, bq, pQ, MROWS, EMB, EMB);
    sgemm_nt_bias<<<gblk, 256>>>(key,   Wk, bk, pK, MROWS, EMB, EMB);
    sgemm_nt_bias<<<gblk, 256>>>(value, Wv, bv, pV, MROWS, EMB, EMB);

    dim3 gattn(SEQ / BQ, NHEAD, BATCH);  // (32, 16, 2)
    flash_attn_kernel<<<gattn, 256, sizeof(AttnSmem)>>>();

    sgemm_nt_bias<<<gblk, 256>>>(pA, Wo, bo, out, MROWS, EMB, EMB);
}

// round 3
// speedup vs baseline: 1.1510x; 1.1510x over previous
#include <cuda_runtime.h>
#include <cuda_bf16.h>
#include <math.h>
#include <stdint.h>

// Problem constants
#define BATCH 2
#define SEQ   2048
#define EMB   1024
#define NHEAD 16
#define HDIM  64
#define MROWS (BATCH*SEQ)   // 4096

// ---------------------------------------------------------------------------
// Scratch (device globals; no runtime allocation allowed)
// ---------------------------------------------------------------------------
__device__ float g_Q[MROWS * EMB];
__device__ float g_K[MROWS * EMB];
__device__ float g_V[MROWS * EMB];
__device__ float g_A[MROWS * EMB];

// ---------------------------------------------------------------------------
// Helpers
// ---------------------------------------------------------------------------
__device__ __forceinline__ uint32_t f2tf32(float x) {
    uint32_t r;
    asm("cvt.rna.tf32.f32 %0, %1;" : "=r"(r) : "f"(x));
    return r;
}

__device__ __forceinline__ void mma_tf32(float* c, const uint32_t* a, const uint32_t* b) {
    asm volatile(
        "mma.sync.aligned.m16n8k8.row.col.f32.tf32.tf32.f32 "
        "{%0,%1,%2,%3}, {%4,%5,%6,%7}, {%8,%9}, {%0,%1,%2,%3};"
        : "+f"(c[0]), "+f"(c[1]), "+f"(c[2]), "+f"(c[3])
        : "r"(a[0]), "r"(a[1]), "r"(a[2]), "r"(a[3]), "r"(b[0]), "r"(b[1]));
}

// ---------------------------------------------------------------------------
// tf32 tensor-core GEMM (mma.sync): C[M,N] = A[M,K] @ W[N,K]^T + bias[N]
// 128x128x32 block, 256 threads (8 warps, each 64x32), double-buffered smem.
// ---------------------------------------------------------------------------
#define GBM 128
#define GBN 128
#define GBK 32
#define PADK 33                      // floats per smem row (pad kills conflicts)
#define STAGE_FLTS (2 * GBM * PADK)  // A tile + B tile per stage
#define GEMM_SMEM_BYTES (2 * STAGE_FLTS * 4)

__global__ __launch_bounds__(256) void gemm_tf32_mma(
    const float* __restrict__ A,     // [M,K]
    const float* __restrict__ W,     // [N,K]
    const float* __restrict__ bias,  // [N]
    float* __restrict__ C,           // [M,N]
    int M, int N, int K)
{
    extern __shared__ float smem[];

    const int tid  = threadIdx.x;
    const int lane = tid & 31;
    const int warp = tid >> 5;
    const int bm = blockIdx.y * GBM;
    const int bn = blockIdx.x * GBN;

    const int wm = (warp >> 2) * 64;   // warp m-offset within block
    const int wn = (warp & 3) * 32;    // warp n-offset within block
    const int gid = lane >> 2;         // 0..7
    const int tig = lane & 3;          // 0..3

    float acc[4][4][4];
#pragma unroll
    for (int mt = 0; mt < 4; mt++)
#pragma unroll
        for (int nt = 0; nt < 4; nt++)
#pragma unroll
            for (int r = 0; r < 4; r++) acc[mt][nt][r] = 0.f;

    // gmem->smem loader: 128x32 tiles of A and W, tf32-converted
    auto load_stage = [&](int s, int k0) {
        float* As = smem + s * STAGE_FLTS;
        float* Bs = As + GBM * PADK;
#pragma unroll
        for (int p = 0; p < 4; p++) {
            int idx = tid + p * 256;       // 0..1023
            int row = idx >> 3;            // 0..127
            int cg  = (idx & 7) * 4;       // 0,4,...,28
            float4 va = *(const float4*)(A + (size_t)(bm + row) * K + k0 + cg);
            float* da = As + row * PADK + cg;
            da[0] = __uint_as_float(f2tf32(va.x));
            da[1] = __uint_as_float(f2tf32(va.y));
            da[2] = __uint_as_float(f2tf32(va.z));
            da[3] = __uint_as_float(f2tf32(va.w));
            float4 vb = *(const float4*)(W + (size_t)(bn + row) * K + k0 + cg);
            float* db = Bs + row * PADK + cg;
            db[0] = __uint_as_float(f2tf32(vb.x));
            db[1] = __uint_as_float(f2tf32(vb.y));
            db[2] = __uint_as_float(f2tf32(vb.z));
            db[3] = __uint_as_float(f2tf32(vb.w));
        }
    };

    const int nchunk = K / GBK;   // 32
    load_stage(0, 0);
    __syncthreads();

    for (int i = 0; i < nchunk; i++) {
        const int s = i & 1;
        if (i + 1 < nchunk) load_stage(s ^ 1, (i + 1) * GBK);

        const float* As = smem + s * STAGE_FLTS;
        const float* Bs = As + GBM * PADK;

#pragma unroll
        for (int ks = 0; ks < 4; ks++) {
            const int kb = ks * 8;
            uint32_t afr[4][4], bfr[4][2];
#pragma unroll
            for (int mt = 0; mt < 4; mt++) {
                const float* p = As + (wm + mt * 16 + gid) * PADK + kb + tig;
                afr[mt][0] = __float_as_uint(p[0]);
                afr[mt][2] = __float_as_uint(p[4]);
                const float* p8 = p + 8 * PADK;
                afr[mt][1] = __float_as_uint(p8[0]);
                afr[mt][3] = __float_as_uint(p8[4]);
            }
#pragma unroll
            for (int nt = 0; nt < 4; nt++) {
                const float* q = Bs + (wn + nt * 8 + gid) * PADK + kb + tig;
                bfr[nt][0] = __float_as_uint(q[0]);
                bfr[nt][1] = __float_as_uint(q[4]);
            }
#pragma unroll
            for (int mt = 0; mt < 4; mt++)
#pragma unroll
                for (int nt = 0; nt < 4; nt++)
                    mma_tf32(acc[mt][nt], afr[mt], bfr[nt]);
        }
        __syncthreads();
    }

    // Epilogue: c0,c1 at (row, col), c2,c3 at (row+8, col); col = nt*8 + tig*2
#pragma unroll
    for (int nt = 0; nt < 4; nt++) {
        const int c0 = bn + wn + nt * 8 + tig * 2;
        const float b0 = bias[c0], b1 = bias[c0 + 1];
#pragma unroll
        for (int mt = 0; mt < 4; mt++) {
            const int r0 = bm + wm + mt * 16 + gid;
            float2 v0 = make_float2(acc[mt][nt][0] + b0, acc[mt][nt][1] + b1);
            float2 v1 = make_float2(acc[mt][nt][2] + b0, acc[mt][nt][3] + b1);
            *(float2*)(C + (size_t)r0 * N + c0) = v0;
            *(float2*)(C + (size_t)(r0 + 8) * N + c0) = v1;
        }
    }
}

// ---------------------------------------------------------------------------
// Flash attention (fp32 SIMT, unchanged from round 1)
// ---------------------------------------------------------------------------
#define BQ 64
#define BKV 64
#define SM_PAD 4
#define SROW (BQ + SM_PAD)   // 68

struct AttnSmem {
    float Qs[HDIM][SROW];
    float Ks[HDIM][SROW];
    float Vs[BKV][HDIM + SM_PAD];
    float Ps[BKV][SROW];
};

__global__ __launch_bounds__(256) void flash_attn_kernel()
{
    extern __shared__ char smem_raw[];
    AttnSmem* sm = reinterpret_cast<AttnSmem*>(smem_raw);

    const int qt = blockIdx.x;
    const int h  = blockIdx.y;
    const int b  = blockIdx.z;

    const float* Qb = g_Q + (size_t)b * SEQ * EMB + h * HDIM;
    const float* Kb = g_K + (size_t)b * SEQ * EMB + h * HDIM;
    const float* Vb = g_V + (size_t)b * SEQ * EMB + h * HDIM;
    float*       Ob = g_A + (size_t)b * SEQ * EMB + h * HDIM;

    const int tid = threadIdx.x;
    const int ty = tid >> 4;
    const int tx = tid & 15;

#pragma unroll
    for (int it = 0; it < 4; it++) {
        int idx = tid + it * 256;
        int q   = idx >> 4;
        int dc  = (idx & 15) * 4;
        float4 v = *(const float4*)(Qb + (size_t)(qt * BQ + q) * EMB + dc);
        sm->Qs[dc + 0][q] = v.x; sm->Qs[dc + 1][q] = v.y;
        sm->Qs[dc + 2][q] = v.z; sm->Qs[dc + 3][q] = v.w;
    }

    float mrow[4], lrow[4], acc[4][4];
#pragma unroll
    for (int i = 0; i < 4; i++) {
        mrow[i] = -1e30f; lrow[i] = 0.f;
#pragma unroll
        for (int j = 0; j < 4; j++) acc[i][j] = 0.f;
    }

    const float scale = 0.125f;

    for (int kt = 0; kt < SEQ / BKV; kt++) {
        __syncthreads();
#pragma unroll
        for (int it = 0; it < 4; it++) {
            int idx = tid + it * 256;
            int kk  = idx >> 4;
            int dc  = (idx & 15) * 4;
            float4 v = *(const float4*)(Kb + (size_t)(kt * BKV + kk) * EMB + dc);
            sm->Ks[dc + 0][kk] = v.x; sm->Ks[dc + 1][kk] = v.y;
            sm->Ks[dc + 2][kk] = v.z; sm->Ks[dc + 3][kk] = v.w;
            float4 w = *(const float4*)(Vb + (size_t)(kt * BKV + kk) * EMB + dc);
            *(float4*)&sm->Vs[kk][dc] = w;
        }
        __syncthreads();

        float s[4][4];
#pragma unroll
        for (int i = 0; i < 4; i++)
#pragma unroll
            for (int j = 0; j < 4; j++) s[i][j] = 0.f;

#pragma unroll
        for (int d = 0; d < HDIM; d++) {
            float4 aq = *(const float4*)&sm->Qs[d][ty * 4];
            float4 bk = *(const float4*)&sm->Ks[d][tx * 4];
            float a[4] = {aq.x, aq.y, aq.z, aq.w};
            float bb[4] = {bk.x, bk.y, bk.z, bk.w};
#pragma unroll
            for (int i = 0; i < 4; i++)
#pragma unroll
                for (int j = 0; j < 4; j++)
                    s[i][j] = fmaf(a[i], bb[j], s[i][j]);
        }
#pragma unroll
        for (int i = 0; i < 4; i++)
#pragma unroll
            for (int j = 0; j < 4; j++) s[i][j] *= scale;

        float p[4][4];
#pragma unroll
        for (int i = 0; i < 4; i++) {
            float rm = fmaxf(fmaxf(s[i][0], s[i][1]), fmaxf(s[i][2], s[i][3]));
#pragma unroll
            for (int o = 8; o >= 1; o >>= 1)
                rm = fmaxf(rm, __shfl_xor_sync(0xffffffffu, rm, o));
            float mnew = fmaxf(mrow[i], rm);
            float corr = __expf(mrow[i] - mnew);
            float rs = 0.f;
#pragma unroll
            for (int j = 0; j < 4; j++) {
                p[i][j] = __expf(s[i][j] - mnew);
                rs += p[i][j];
            }
#pragma unroll
            for (int o = 8; o >= 1; o >>= 1)
                rs += __shfl_xor_sync(0xffffffffu, rs, o);
            lrow[i] = lrow[i] * corr + rs;
            mrow[i] = mnew;
#pragma unroll
            for (int j = 0; j < 4; j++) acc[i][j] *= corr;
        }

#pragma unroll
        for (int i = 0; i < 4; i++)
#pragma unroll
            for (int j = 0; j < 4; j++)
                sm->Ps[tx * 4 + j][ty * 4 + i] = p[i][j];
        __syncthreads();

#pragma unroll
        for (int k = 0; k < BKV; k++) {
            float4 pq = *(const float4*)&sm->Ps[k][ty * 4];
            float4 vv = *(const float4*)&sm->Vs[k][tx * 4];
            float pp[4] = {pq.x, pq.y, pq.z, pq.w};
            float vvv[4] = {vv.x, vv.y, vv.z, vv.w};
#pragma unroll
            for (int i = 0; i < 4; i++)
#pragma unroll
                for (int j = 0; j < 4; j++)
                    acc[i][j] = fmaf(pp[i], vvv[j], acc[i][j]);
        }
    }

#pragma unroll
    for (int i = 0; i < 4; i++) {
        float inv = 1.0f / lrow[i];
        float4 v;
        v.x = acc[i][0] * inv; v.y = acc[i][1] * inv;
        v.z = acc[i][2] * inv; v.w = acc[i][3] * inv;
        *(float4*)(Ob + (size_t)(qt * BQ + ty * 4 + i) * EMB + tx * 4) = v;
    }
}

// ---------------------------------------------------------------------------
// Launch
// ---------------------------------------------------------------------------
extern "C" void kernel_launch(void* const* d_in, const int* in_sizes, int n_in,
                              void* d_out, int out_size)
{
    const float* query = (const float*)d_in[0];
    const float* key   = (const float*)d_in[1];
    const float* value = (const float*)d_in[2];
    const float* Wq    = (const float*)d_in[3];
    const float* bq    = (const float*)d_in[4];
    const float* Wk    = (const float*)d_in[5];
    const float* bk    = (const float*)d_in[6];
    const float* Wv    = (const float*)d_in[7];
    const float* bv    = (const float*)d_in[8];
    const float* Wo    = (const float*)d_in[9];
    const float* bo    = (const float*)d_in[10];
    float* out = (float*)d_out;

    float *pQ, *pK, *pV, *pA;
    cudaGetSymbolAddress((void**)&pQ, g_Q);
    cudaGetSymbolAddress((void**)&pK, g_K);
    cudaGetSymbolAddress((void**)&pV, g_V);
    cudaGetSymbolAddress((void**)&pA, g_A);

    cudaFuncSetAttribute(gemm_tf32_mma,
                         cudaFuncAttributeMaxDynamicSharedMemorySize,
                         GEMM_SMEM_BYTES);
    cudaFuncSetAttribute(flash_attn_kernel,
                         cudaFuncAttributeMaxDynamicSharedMemorySize,
                         (int)sizeof(AttnSmem));

    dim3 gblk(EMB / GBN, MROWS / GBM);   // (8, 32)

    gemm_tf32_mma<<<gblk, 256, GEMM_SMEM_BYTES>>>(query, Wq, bq, pQ, MROWS, EMB, EMB);
    gemm_tf32_mma<<<gblk, 256, GEMM_SMEM_BYTES>>>(key,   Wk, bk, pK, MROWS, EMB, EMB);
    gemm_tf32_mma<<<gblk, 256, GEMM_SMEM_BYTES>>>(value, Wv, bv, pV, MROWS, EMB, EMB);

    dim3 gattn(SEQ / BQ, NHEAD, BATCH);  // (32, 16, 2)
    flash_attn_kernel<<<gattn, 256, sizeof(AttnSmem)>>>();

    gemm_tf32_mma<<<gblk, 256, GEMM_SMEM_BYTES>>>(pA, Wo, bo, out, MROWS, EMB, EMB);
}

// round 4
// speedup vs baseline: 2.7947x; 2.4280x over previous
#include <cuda_runtime.h>
#include <cuda_bf16.h>
#include <math.h>
#include <stdint.h>

// Problem constants
#define BATCH 2
#define SEQ   2048
#define EMB   1024
#define NHEAD 16
#define HDIM  64
#define MROWS (BATCH*SEQ)   // 4096

// ---------------------------------------------------------------------------
// Scratch (device globals; no runtime allocation allowed)
// ---------------------------------------------------------------------------
__device__ float g_Q[MROWS * EMB];
__device__ float g_K[MROWS * EMB];
__device__ float g_V[MROWS * EMB];
__device__ float g_A[MROWS * EMB];

// ---------------------------------------------------------------------------
// Helpers
// ---------------------------------------------------------------------------
__device__ __forceinline__ uint32_t f2tf32(float x) {
    uint32_t r;
    asm("cvt.rna.tf32.f32 %0, %1;" : "=r"(r) : "f"(x));
    return r;
}
__device__ __forceinline__ float f2tf32f(float x) {
    return __uint_as_float(f2tf32(x));
}
__device__ __forceinline__ float fexp2(float x) {
    float r;
    asm("ex2.approx.ftz.f32 %0, %1;" : "=f"(r) : "f"(x));
    return r;
}

__device__ __forceinline__ void mma_tf32(float* c, const uint32_t* a, const uint32_t* b) {
    asm volatile(
        "mma.sync.aligned.m16n8k8.row.col.f32.tf32.tf32.f32 "
        "{%0,%1,%2,%3}, {%4,%5,%6,%7}, {%8,%9}, {%0,%1,%2,%3};"
        : "+f"(c[0]), "+f"(c[1]), "+f"(c[2]), "+f"(c[3])
        : "r"(a[0]), "r"(a[1]), "r"(a[2]), "r"(a[3]), "r"(b[0]), "r"(b[1]));
}

// ---------------------------------------------------------------------------
// tf32 tensor-core GEMM (mma.sync): C[M,N] = A[M,K] @ W[N,K]^T + bias[N]
// 128x128x32 block, 256 threads (8 warps, each 64x32), double-buffered smem.
// PADK=36: fragment LDS bank = (4*gid + tig) % 32 -> conflict-free.
// ---------------------------------------------------------------------------
#define GBM 128
#define GBN 128
#define GBK 32
#define PADK 36
#define STAGE_FLTS (2 * GBM * PADK)
#define GEMM_SMEM_BYTES (2 * STAGE_FLTS * 4)   // 73728

__global__ __launch_bounds__(256) void gemm_tf32_mma(
    const float* __restrict__ A,     // [M,K]
    const float* __restrict__ W,     // [N,K]
    const float* __restrict__ bias,  // [N]
    float* __restrict__ C,           // [M,N]
    int M, int N, int K)
{
    extern __shared__ float smem[];

    const int tid  = threadIdx.x;
    const int lane = tid & 31;
    const int warp = tid >> 5;
    const int bm = blockIdx.y * GBM;
    const int bn = blockIdx.x * GBN;

    const int wm = (warp >> 2) * 64;
    const int wn = (warp & 3) * 32;
    const int gid = lane >> 2;
    const int tig = lane & 3;

    float acc[4][4][4];
#pragma unroll
    for (int mt = 0; mt < 4; mt++)
#pragma unroll
        for (int nt = 0; nt < 4; nt++)
#pragma unroll
            for (int r = 0; r < 4; r++) acc[mt][nt][r] = 0.f;

    auto load_stage = [&](int s, int k0) {
        float* As = smem + s * STAGE_FLTS;
        float* Bs = As + GBM * PADK;
#pragma unroll
        for (int p = 0; p < 4; p++) {
            int idx = tid + p * 256;
            int row = idx >> 3;
            int cg  = (idx & 7) * 4;
            float4 va = *(const float4*)(A + (size_t)(bm + row) * K + k0 + cg);
            float* da = As + row * PADK + cg;
            da[0] = f2tf32f(va.x); da[1] = f2tf32f(va.y);
            da[2] = f2tf32f(va.z); da[3] = f2tf32f(va.w);
            float4 vb = *(const float4*)(W + (size_t)(bn + row) * K + k0 + cg);
            float* db = Bs + row * PADK + cg;
            db[0] = f2tf32f(vb.x); db[1] = f2tf32f(vb.y);
            db[2] = f2tf32f(vb.z); db[3] = f2tf32f(vb.w);
        }
    };

    const int nchunk = K / GBK;
    load_stage(0, 0);
    __syncthreads();

    for (int i = 0; i < nchunk; i++) {
        const int s = i & 1;
        if (i + 1 < nchunk) load_stage(s ^ 1, (i + 1) * GBK);

        const float* As = smem + s * STAGE_FLTS;
        const float* Bs = As + GBM * PADK;

#pragma unroll
        for (int ks = 0; ks < 4; ks++) {
            const int kb = ks * 8;
            uint32_t afr[4][4], bfr[4][2];
#pragma unroll
            for (int mt = 0; mt < 4; mt++) {
                const float* p = As + (wm + mt * 16 + gid) * PADK + kb + tig;
                afr[mt][0] = __float_as_uint(p[0]);
                afr[mt][2] = __float_as_uint(p[4]);
                const float* p8 = p + 8 * PADK;
                afr[mt][1] = __float_as_uint(p8[0]);
                afr[mt][3] = __float_as_uint(p8[4]);
            }
#pragma unroll
            for (int nt = 0; nt < 4; nt++) {
                const float* q = Bs + (wn + nt * 8 + gid) * PADK + kb + tig;
                bfr[nt][0] = __float_as_uint(q[0]);
                bfr[nt][1] = __float_as_uint(q[4]);
            }
#pragma unroll
            for (int mt = 0; mt < 4; mt++)
#pragma unroll
                for (int nt = 0; nt < 4; nt++)
                    mma_tf32(acc[mt][nt], afr[mt], bfr[nt]);
        }
        __syncthreads();
    }

#pragma unroll
    for (int nt = 0; nt < 4; nt++) {
        const int c0 = bn + wn + nt * 8 + tig * 2;
        const float b0 = bias[c0], b1 = bias[c0 + 1];
#pragma unroll
        for (int mt = 0; mt < 4; mt++) {
            const int r0 = bm + wm + mt * 16 + gid;
            float2 v0 = make_float2(acc[mt][nt][0] + b0, acc[mt][nt][1] + b1);
            float2 v1 = make_float2(acc[mt][nt][2] + b0, acc[mt][nt][3] + b1);
            *(float2*)(C + (size_t)r0 * N + c0) = v0;
            *(float2*)(C + (size_t)(r0 + 8) * N + c0) = v1;
        }
    }
}

// ---------------------------------------------------------------------------
// Flash attention on mma.sync tf32.
// CTA: 128 q rows x full 2048 keys in 64-key tiles. 256 threads, 8 warps,
// each warp owns 16 q rows. Online softmax in exp2 domain (scale*log2e folded
// into Q at load). K/V register-prefetch double buffering.
// smem rows padded to 68 floats: fragment LDS bank = (4*gid+tig)%32, conflict-free.
// ---------------------------------------------------------------------------
#define AQ   128
#define AKV  64
#define APAD 68
#define ATTN_SMEM_FLTS ((AQ + AKV + HDIM + AQ) * APAD)
#define ATTN_SMEM_BYTES (ATTN_SMEM_FLTS * 4)   // 104448

__global__ __launch_bounds__(256, 2) void flash_attn_mma()
{
    extern __shared__ float dsm[];
    float (*Qs)[APAD] = (float(*)[APAD])dsm;            // [q][hd]
    float (*Ks)[APAD] = (float(*)[APAD])(dsm + AQ * APAD);        // [key][hd]
    float (*Vt)[APAD] = (float(*)[APAD])(dsm + (AQ + AKV) * APAD); // [hd][key]
    float (*Ps)[APAD] = (float(*)[APAD])(dsm + (AQ + AKV + HDIM) * APAD); // [q][key]

    const int qt = blockIdx.x;
    const int h  = blockIdx.y;
    const int b  = blockIdx.z;

    const float* Qb = g_Q + ((size_t)b * SEQ + qt * AQ) * EMB + h * HDIM;
    const float* Kb = g_K + (size_t)b * SEQ * EMB + h * HDIM;
    const float* Vb = g_V + (size_t)b * SEQ * EMB + h * HDIM;
    float*       Ob = g_A + ((size_t)b * SEQ + qt * AQ) * EMB + h * HDIM;

    const int tid  = threadIdx.x;
    const int lane = tid & 31;
    const int warp = tid >> 5;
    const int gid  = lane >> 2;
    const int tig  = lane & 3;
    const int wm   = warp * 16;

    // Load Q tile (128x64), fold softmax scale * log2(e), round to tf32.
    const float qscale = 0.125f * 1.4426950408889634f;
#pragma unroll
    for (int p = 0; p < 8; p++) {
        int idx = tid + p * 256;       // 0..2047
        int row = idx >> 4;            // 0..127
        int c4  = (idx & 15) * 4;
        float4 v = *(const float4*)(Qb + (size_t)row * EMB + c4);
        float* d = &Qs[row][c4];
        d[0] = f2tf32f(v.x * qscale); d[1] = f2tf32f(v.y * qscale);
        d[2] = f2tf32f(v.z * qscale); d[3] = f2tf32f(v.w * qscale);
    }

    float oacc[8][4];
#pragma unroll
    for (int nt = 0; nt < 8; nt++)
#pragma unroll
        for (int r = 0; r < 4; r++) oacc[nt][r] = 0.f;
    float m0 = -1e30f, m1 = -1e30f, l0 = 0.f, l1 = 0.f;

    // Prefetch tile 0: K and V, 4 float4 each per thread.
    float4 pk[4], pv[4];
#pragma unroll
    for (int p = 0; p < 4; p++) {
        int idx = tid + p * 256;       // 0..1023
        int row = idx >> 4;            // 0..63
        int c4  = (idx & 15) * 4;
        pk[p] = *(const float4*)(Kb + (size_t)row * EMB + c4);
        pv[p] = *(const float4*)(Vb + (size_t)row * EMB + c4);
    }

    const int ntile = SEQ / AKV;   // 32
    for (int kt = 0; kt < ntile; kt++) {
        __syncthreads();   // previous tile's smem reads complete
        // Stage K (natural) and V (transposed), tf32-rounded.
#pragma unroll
        for (int p = 0; p < 4; p++) {
            int idx = tid + p * 256;
            int row = idx >> 4;
            int c4  = (idx & 15) * 4;
            float* dk = &Ks[row][c4];
            dk[0] = f2tf32f(pk[p].x); dk[1] = f2tf32f(pk[p].y);
            dk[2] = f2tf32f(pk[p].z); dk[3] = f2tf32f(pk[p].w);
            Vt[c4 + 0][row] = f2tf32f(pv[p].x);
            Vt[c4 + 1][row] = f2tf32f(pv[p].y);
            Vt[c4 + 2][row] = f2tf32f(pv[p].z);
            Vt[c4 + 3][row] = f2tf32f(pv[p].w);
        }
        __syncthreads();

        // Prefetch next tile while computing this one.
        if (kt + 1 < ntile) {
            const float* Kn = Kb + (size_t)(kt + 1) * AKV * EMB;
            const float* Vn = Vb + (size_t)(kt + 1) * AKV * EMB;
#pragma unroll
            for (int p = 0; p < 4; p++) {
                int idx = tid + p * 256;
                int row = idx >> 4;
                int c4  = (idx & 15) * 4;
                pk[p] = *(const float4*)(Kn + (size_t)row * EMB + c4);
                pv[p] = *(const float4*)(Vn + (size_t)row * EMB + c4);
            }
        }

        // S = Q K^T for this warp's 16 rows x 64 keys (8 n-tiles).
        float sacc[8][4];
#pragma unroll
        for (int nt = 0; nt < 8; nt++)
#pragma unroll
            for (int r = 0; r < 4; r++) sacc[nt][r] = 0.f;

#pragma unroll
        for (int ks = 0; ks < 8; ks++) {
            const int kb = ks * 8;
            uint32_t a[4];
            const float* ap = &Qs[wm + gid][kb + tig];
            a[0] = __float_as_uint(ap[0]);
            a[2] = __float_as_uint(ap[4]);
            const float* ap8 = &Qs[wm + gid + 8][kb + tig];
            a[1] = __float_as_uint(ap8[0]);
            a[3] = __float_as_uint(ap8[4]);
#pragma unroll
            for (int nt = 0; nt < 8; nt++) {
                uint32_t bf[2];
                const float* bp = &Ks[nt * 8 + gid][kb + tig];
                bf[0] = __float_as_uint(bp[0]);
                bf[1] = __float_as_uint(bp[4]);
                mma_tf32(sacc[nt], a, bf);
            }
        }

        // Online softmax (exp2 domain). Row r0=gid holds sacc[*][0,1],
        // row r1=gid+8 holds sacc[*][2,3]. Row spread across tig group.
        float mx0 = -1e30f, mx1 = -1e30f;
#pragma unroll
        for (int nt = 0; nt < 8; nt++) {
            mx0 = fmaxf(mx0, fmaxf(sacc[nt][0], sacc[nt][1]));
            mx1 = fmaxf(mx1, fmaxf(sacc[nt][2], sacc[nt][3]));
        }
        mx0 = fmaxf(mx0, __shfl_xor_sync(0xffffffffu, mx0, 1));
        mx0 = fmaxf(mx0, __shfl_xor_sync(0xffffffffu, mx0, 2));
        mx1 = fmaxf(mx1, __shfl_xor_sync(0xffffffffu, mx1, 1));
        mx1 = fmaxf(mx1, __shfl_xor_sync(0xffffffffu, mx1, 2));

        float mn0 = fmaxf(m0, mx0), mn1 = fmaxf(m1, mx1);
        float corr0 = fexp2(m0 - mn0), corr1 = fexp2(m1 - mn1);
        float s0 = 0.f, s1 = 0.f;
#pragma unroll
        for (int nt = 0; nt < 8; nt++) {
            sacc[nt][0] = fexp2(sacc[nt][0] - mn0);
            sacc[nt][1] = fexp2(sacc[nt][1] - mn0);
            sacc[nt][2] = fexp2(sacc[nt][2] - mn1);
            sacc[nt][3] = fexp2(sacc[nt][3] - mn1);
            s0 += sacc[nt][0] + sacc[nt][1];
            s1 += sacc[nt][2] + sacc[nt][3];
        }
        s0 += __shfl_xor_sync(0xffffffffu, s0, 1);
        s0 += __shfl_xor_sync(0xffffffffu, s0, 2);
        s1 += __shfl_xor_sync(0xffffffffu, s1, 1);
        s1 += __shfl_xor_sync(0xffffffffu, s1, 2);
        l0 = l0 * corr0 + s0;  m0 = mn0;
        l1 = l1 * corr1 + s1;  m1 = mn1;
#pragma unroll
        for (int nt = 0; nt < 8; nt++) {
            oacc[nt][0] *= corr0; oacc[nt][1] *= corr0;
            oacc[nt][2] *= corr1; oacc[nt][3] *= corr1;
        }

        // Stage P (tf32-rounded) into this warp's private rows of Ps.
#pragma unroll
        for (int nt = 0; nt < 8; nt++) {
            float2 v0 = make_float2(f2tf32f(sacc[nt][0]), f2tf32f(sacc[nt][1]));
            float2 v1 = make_float2(f2tf32f(sacc[nt][2]), f2tf32f(sacc[nt][3]));
            *(float2*)&Ps[wm + gid][nt * 8 + tig * 2] = v0;
            *(float2*)&Ps[wm + gid + 8][nt * 8 + tig * 2] = v1;
        }
        __syncwarp();

        // O += P V : A = Ps (warp rows), B = Vt, 8 hd n-tiles, 8 k-steps.
#pragma unroll
        for (int ks = 0; ks < 8; ks++) {
            const int kb = ks * 8;
            uint32_t a[4];
            const float* ap = &Ps[wm + gid][kb + tig];
            a[0] = __float_as_uint(ap[0]);
            a[2] = __float_as_uint(ap[4]);
            const float* ap8 = &Ps[wm + gid + 8][kb + tig];
            a[1] = __float_as_uint(ap8[0]);
            a[3] = __float_as_uint(ap8[4]);
#pragma unroll
            for (int nt = 0; nt < 8; nt++) {
                uint32_t bf[2];
                const float* bp = &Vt[nt * 8 + gid][kb + tig];
                bf[0] = __float_as_uint(bp[0]);
                bf[1] = __float_as_uint(bp[4]);
                mma_tf32(oacc[nt], a, bf);
            }
        }
    }

    // Epilogue: normalize and write.
    const float inv0 = 1.0f / l0, inv1 = 1.0f / l1;
    const int r0 = wm + gid, r1 = wm + gid + 8;
#pragma unroll
    for (int nt = 0; nt < 8; nt++) {
        const int c = nt * 8 + tig * 2;
        float2 v0 = make_float2(oacc[nt][0] * inv0, oacc[nt][1] * inv0);
        float2 v1 = make_float2(oacc[nt][2] * inv1, oacc[nt][3] * inv1);
        *(float2*)(Ob + (size_t)r0 * EMB + c) = v0;
        *(float2*)(Ob + (size_t)r1 * EMB + c) = v1;
    }
}

// ---------------------------------------------------------------------------
// Launch
// ---------------------------------------------------------------------------
extern "C" void kernel_launch(void* const* d_in, const int* in_sizes, int n_in,
                              void* d_out, int out_size)
{
    const float* query = (const float*)d_in[0];
    const float* key   = (const float*)d_in[1];
    const float* value = (const float*)d_in[2];
    const float* Wq    = (const float*)d_in[3];
    const float* bq    = (const float*)d_in[4];
    const float* Wk    = (const float*)d_in[5];
    const float* bk    = (const float*)d_in[6];
    const float* Wv    = (const float*)d_in[7];
    const float* bv    = (const float*)d_in[8];
    const float* Wo    = (const float*)d_in[9];
    const float* bo    = (const float*)d_in[10];
    float* out = (float*)d_out;

    float *pQ, *pK, *pV, *pA;
    cudaGetSymbolAddress((void**)&pQ, g_Q);
    cudaGetSymbolAddress((void**)&pK, g_K);
    cudaGetSymbolAddress((void**)&pV, g_V);
    cudaGetSymbolAddress((void**)&pA, g_A);

    cudaFuncSetAttribute(gemm_tf32_mma,
                         cudaFuncAttributeMaxDynamicSharedMemorySize,
                         GEMM_SMEM_BYTES);
    cudaFuncSetAttribute(flash_attn_mma,
                         cudaFuncAttributeMaxDynamicSharedMemorySize,
                         ATTN_SMEM_BYTES);

    dim3 gblk(EMB / GBN, MROWS / GBM);   // (8, 32)

    gemm_tf32_mma<<<gblk, 256, GEMM_SMEM_BYTES>>>(query, Wq, bq, pQ, MROWS, EMB, EMB);
    gemm_tf32_mma<<<gblk, 256, GEMM_SMEM_BYTES>>>(key,   Wk, bk, pK, MROWS, EMB, EMB);
    gemm_tf32_mma<<<gblk, 256, GEMM_SMEM_BYTES>>>(value, Wv, bv, pV, MROWS, EMB, EMB);

    dim3 gattn(SEQ / AQ, NHEAD, BATCH);  // (16, 16, 2)
    flash_attn_mma<<<gattn, 256, ATTN_SMEM_BYTES>>>();

    gemm_tf32_mma<<<gblk, 256, GEMM_SMEM_BYTES>>>(pA, Wo, bo, out, MROWS, EMB, EMB);
}

// round 5
// speedup vs baseline: 3.0250x; 1.0824x over previous
#include <cuda_runtime.h>
#include <cuda_bf16.h>
#include <math.h>
#include <stdint.h>

// Problem constants
#define BATCH 2
#define SEQ   2048
#define EMB   1024
#define NHEAD 16
#define HDIM  64
#define MROWS (BATCH*SEQ)   // 4096

// ---------------------------------------------------------------------------
// Scratch (device globals; no runtime allocation allowed)
// ---------------------------------------------------------------------------
__device__ float g_Q[MROWS * EMB];
__device__ float g_K[MROWS * EMB];
__device__ float g_V[MROWS * EMB];
__device__ float g_A[MROWS * EMB];

// ---------------------------------------------------------------------------
// Helpers
// ---------------------------------------------------------------------------
__device__ __forceinline__ uint32_t f2tf32(float x) {
    uint32_t r;
    asm("cvt.rna.tf32.f32 %0, %1;" : "=r"(r) : "f"(x));
    return r;
}
__device__ __forceinline__ float f2tf32f(float x) {
    return __uint_as_float(f2tf32(x));
}
__device__ __forceinline__ float fexp2(float x) {
    float r;
    asm("ex2.approx.ftz.f32 %0, %1;" : "=f"(r) : "f"(x));
    return r;
}

__device__ __forceinline__ void mma_tf32(float* c, const uint32_t* a, const uint32_t* b) {
    asm volatile(
        "mma.sync.aligned.m16n8k8.row.col.f32.tf32.tf32.f32 "
        "{%0,%1,%2,%3}, {%4,%5,%6,%7}, {%8,%9}, {%0,%1,%2,%3};"
        : "+f"(c[0]), "+f"(c[1]), "+f"(c[2]), "+f"(c[3])
        : "r"(a[0]), "r"(a[1]), "r"(a[2]), "r"(a[3]), "r"(b[0]), "r"(b[1]));
}

// ---------------------------------------------------------------------------
// tf32 tensor-core GEMM (mma.sync): C[M,N] = A[M,K] @ W[N,K]^T + bias[N]
// 128x128x32 block, 256 threads (8 warps, each 64x32), double-buffered smem.
// ---------------------------------------------------------------------------
#define GBM 128
#define GBN 128
#define GBK 32
#define PADK 36
#define STAGE_FLTS (2 * GBM * PADK)
#define GEMM_SMEM_BYTES (2 * STAGE_FLTS * 4)   // 73728

__global__ __launch_bounds__(256) void gemm_tf32_mma(
    const float* __restrict__ A,     // [M,K]
    const float* __restrict__ W,     // [N,K]
    const float* __restrict__ bias,  // [N]
    float* __restrict__ C,           // [M,N]
    int M, int N, int K)
{
    extern __shared__ float smem[];

    const int tid  = threadIdx.x;
    const int lane = tid & 31;
    const int warp = tid >> 5;
    const int bm = blockIdx.y * GBM;
    const int bn = blockIdx.x * GBN;

    const int wm = (warp >> 2) * 64;
    const int wn = (warp & 3) * 32;
    const int gid = lane >> 2;
    const int tig = lane & 3;

    float acc[4][4][4];
#pragma unroll
    for (int mt = 0; mt < 4; mt++)
#pragma unroll
        for (int nt = 0; nt < 4; nt++)
#pragma unroll
            for (int r = 0; r < 4; r++) acc[mt][nt][r] = 0.f;

    auto load_stage = [&](int s, int k0) {
        float* As = smem + s * STAGE_FLTS;
        float* Bs = As + GBM * PADK;
#pragma unroll
        for (int p = 0; p < 4; p++) {
            int idx = tid + p * 256;
            int row = idx >> 3;
            int cg  = (idx & 7) * 4;
            float4 va = *(const float4*)(A + (size_t)(bm + row) * K + k0 + cg);
            float* da = As + row * PADK + cg;
            da[0] = f2tf32f(va.x); da[1] = f2tf32f(va.y);
            da[2] = f2tf32f(va.z); da[3] = f2tf32f(va.w);
            float4 vb = *(const float4*)(W + (size_t)(bn + row) * K + k0 + cg);
            float* db = Bs + row * PADK + cg;
            db[0] = f2tf32f(vb.x); db[1] = f2tf32f(vb.y);
            db[2] = f2tf32f(vb.z); db[3] = f2tf32f(vb.w);
        }
    };

    const int nchunk = K / GBK;
    load_stage(0, 0);
    __syncthreads();

    for (int i = 0; i < nchunk; i++) {
        const int s = i & 1;
        if (i + 1 < nchunk) load_stage(s ^ 1, (i + 1) * GBK);

        const float* As = smem + s * STAGE_FLTS;
        const float* Bs = As + GBM * PADK;

#pragma unroll
        for (int ks = 0; ks < 4; ks++) {
            const int kb = ks * 8;
            uint32_t afr[4][4], bfr[4][2];
#pragma unroll
            for (int mt = 0; mt < 4; mt++) {
                const float* p = As + (wm + mt * 16 + gid) * PADK + kb + tig;
                afr[mt][0] = __float_as_uint(p[0]);
                afr[mt][2] = __float_as_uint(p[4]);
                const float* p8 = p + 8 * PADK;
                afr[mt][1] = __float_as_uint(p8[0]);
                afr[mt][3] = __float_as_uint(p8[4]);
            }
#pragma unroll
            for (int nt = 0; nt < 4; nt++) {
                const float* q = Bs + (wn + nt * 8 + gid) * PADK + kb + tig;
                bfr[nt][0] = __float_as_uint(q[0]);
                bfr[nt][1] = __float_as_uint(q[4]);
            }
#pragma unroll
            for (int mt = 0; mt < 4; mt++)
#pragma unroll
                for (int nt = 0; nt < 4; nt++)
                    mma_tf32(acc[mt][nt], afr[mt], bfr[nt]);
        }
        __syncthreads();
    }

#pragma unroll
    for (int nt = 0; nt < 4; nt++) {
        const int c0 = bn + wn + nt * 8 + tig * 2;
        const float b0 = bias[c0], b1 = bias[c0 + 1];
#pragma unroll
        for (int mt = 0; mt < 4; mt++) {
            const int r0 = bm + wm + mt * 16 + gid;
            float2 v0 = make_float2(acc[mt][nt][0] + b0, acc[mt][nt][1] + b1);
            float2 v1 = make_float2(acc[mt][nt][2] + b0, acc[mt][nt][3] + b1);
            *(float2*)(C + (size_t)r0 * N + c0) = v0;
            *(float2*)(C + (size_t)(r0 + 8) * N + c0) = v1;
        }
    }
}

// ---------------------------------------------------------------------------
// Flash attention, mma.sync tf32, v2.
// CTA: 128 q rows, 128 threads, 4 warps; each warp owns 32 q rows (mt=2).
// K/V tiles of 64 keys. Q fragments hoisted to registers (read once).
// V stored natural [key][hd]; PV B-fragments read transposed (<=2-way).
// Register prefetch of next K/V issued after softmax (caps live regs).
// ---------------------------------------------------------------------------
#define AQ   128
#define AKV  64
#define APAD 68
#define ATTN_SMEM_FLTS ((AQ + AKV + AKV + AQ) * APAD)
#define ATTN_SMEM_BYTES (ATTN_SMEM_FLTS * 4)   // 104448

__global__ __launch_bounds__(128, 2) void flash_attn_mma()
{
    extern __shared__ float dsm[];
    float (*Qs)[APAD] = (float(*)[APAD])dsm;                         // [q][hd]
    float (*Ks)[APAD] = (float(*)[APAD])(dsm + AQ * APAD);           // [key][hd]
    float (*Vs)[APAD] = (float(*)[APAD])(dsm + (AQ + AKV) * APAD);   // [key][hd]
    float (*Ps)[APAD] = (float(*)[APAD])(dsm + (AQ + 2 * AKV) * APAD); // [q][key]

    const int qt = blockIdx.x;
    const int h  = blockIdx.y;
    const int b  = blockIdx.z;

    const float* Qb = g_Q + ((size_t)b * SEQ + qt * AQ) * EMB + h * HDIM;
    const float* Kb = g_K + (size_t)b * SEQ * EMB + h * HDIM;
    const float* Vb = g_V + (size_t)b * SEQ * EMB + h * HDIM;
    float*       Ob = g_A + ((size_t)b * SEQ + qt * AQ) * EMB + h * HDIM;

    const int tid  = threadIdx.x;
    const int lane = tid & 31;
    const int warp = tid >> 5;
    const int gid  = lane >> 2;
    const int tig  = lane & 3;
    const int wm   = warp * 32;

    // Stage Q (128x64), fold softmax scale * log2(e), round to tf32.
    const float qscale = 0.125f * 1.4426950408889634f;
#pragma unroll
    for (int p = 0; p < 16; p++) {
        int idx = tid + p * 128;       // 0..2047
        int row = idx >> 4;            // 0..127
        int c4  = (idx & 15) * 4;
        float4 v = *(const float4*)(Qb + (size_t)row * EMB + c4);
        float* d = &Qs[row][c4];
        d[0] = f2tf32f(v.x * qscale); d[1] = f2tf32f(v.y * qscale);
        d[2] = f2tf32f(v.z * qscale); d[3] = f2tf32f(v.w * qscale);
    }
    __syncthreads();

    // Hoist Q fragments into registers (read once for all 32 tiles).
    uint32_t qfr[2][8][4];
#pragma unroll
    for (int mt = 0; mt < 2; mt++)
#pragma unroll
        for (int ks = 0; ks < 8; ks++) {
            const float* ap = &Qs[wm + mt * 16 + gid][ks * 8 + tig];
            qfr[mt][ks][0] = __float_as_uint(ap[0]);
            qfr[mt][ks][2] = __float_as_uint(ap[4]);
            const float* ap8 = &Qs[wm + mt * 16 + gid + 8][ks * 8 + tig];
            qfr[mt][ks][1] = __float_as_uint(ap8[0]);
            qfr[mt][ks][3] = __float_as_uint(ap8[4]);
        }

    float oacc[2][8][4];
#pragma unroll
    for (int mt = 0; mt < 2; mt++)
#pragma unroll
        for (int nt = 0; nt < 8; nt++)
#pragma unroll
            for (int r = 0; r < 4; r++) oacc[mt][nt][r] = 0.f;
    float mrow[2][2], lrow[2][2];
#pragma unroll
    for (int mt = 0; mt < 2; mt++) {
        mrow[mt][0] = -1e30f; mrow[mt][1] = -1e30f;
        lrow[mt][0] = 0.f;    lrow[mt][1] = 0.f;
    }

    // Prefetch tile 0: K and V, 8 float4 each per thread.
    float4 pk[8], pv[8];
#pragma unroll
    for (int p = 0; p < 8; p++) {
        int idx = tid + p * 128;       // 0..1023
        int row = idx >> 4;            // 0..63
        int c4  = (idx & 15) * 4;
        pk[p] = *(const float4*)(Kb + (size_t)row * EMB + c4);
        pv[p] = *(const float4*)(Vb + (size_t)row * EMB + c4);
    }

    const int ntile = SEQ / AKV;   // 32
    for (int kt = 0; kt < ntile; kt++) {
        __syncthreads();   // previous tile's smem reads complete
        // Stage K and V, both natural [key][hd], tf32-rounded, STS.128.
#pragma unroll
        for (int p = 0; p < 8; p++) {
            int idx = tid + p * 128;
            int row = idx >> 4;
            int c4  = (idx & 15) * 4;
            float4 tk = make_float4(f2tf32f(pk[p].x), f2tf32f(pk[p].y),
                                    f2tf32f(pk[p].z), f2tf32f(pk[p].w));
            *(float4*)&Ks[row][c4] = tk;
            float4 tv = make_float4(f2tf32f(pv[p].x), f2tf32f(pv[p].y),
                                    f2tf32f(pv[p].z), f2tf32f(pv[p].w));
            *(float4*)&Vs[row][c4] = tv;
        }
        __syncthreads();

        // S = Q K^T for this warp's 32 rows x 64 keys.
        float sacc[2][8][4];
#pragma unroll
        for (int mt = 0; mt < 2; mt++)
#pragma unroll
            for (int nt = 0; nt < 8; nt++)
#pragma unroll
                for (int r = 0; r < 4; r++) sacc[mt][nt][r] = 0.f;

#pragma unroll
        for (int ks = 0; ks < 8; ks++) {
            const int kb = ks * 8;
#pragma unroll
            for (int nt = 0; nt < 8; nt++) {
                uint32_t bf[2];
                const float* bp = &Ks[nt * 8 + gid][kb + tig];
                bf[0] = __float_as_uint(bp[0]);
                bf[1] = __float_as_uint(bp[4]);
                mma_tf32(sacc[0][nt], qfr[0][ks], bf);
                mma_tf32(sacc[1][nt], qfr[1][ks], bf);
            }
        }

        // Online softmax (exp2 domain) per mt row-pair.
#pragma unroll
        for (int mt = 0; mt < 2; mt++) {
            float mx0 = -1e30f, mx1 = -1e30f;
#pragma unroll
            for (int nt = 0; nt < 8; nt++) {
                mx0 = fmaxf(mx0, fmaxf(sacc[mt][nt][0], sacc[mt][nt][1]));
                mx1 = fmaxf(mx1, fmaxf(sacc[mt][nt][2], sacc[mt][nt][3]));
            }
            mx0 = fmaxf(mx0, __shfl_xor_sync(0xffffffffu, mx0, 1));
            mx0 = fmaxf(mx0, __shfl_xor_sync(0xffffffffu, mx0, 2));
            mx1 = fmaxf(mx1, __shfl_xor_sync(0xffffffffu, mx1, 1));
            mx1 = fmaxf(mx1, __shfl_xor_sync(0xffffffffu, mx1, 2));

            float mn0 = fmaxf(mrow[mt][0], mx0), mn1 = fmaxf(mrow[mt][1], mx1);
            float corr0 = fexp2(mrow[mt][0] - mn0), corr1 = fexp2(mrow[mt][1] - mn1);
            float s0 = 0.f, s1 = 0.f;
#pragma unroll
            for (int nt = 0; nt < 8; nt++) {
                sacc[mt][nt][0] = fexp2(sacc[mt][nt][0] - mn0);
                sacc[mt][nt][1] = fexp2(sacc[mt][nt][1] - mn0);
                sacc[mt][nt][2] = fexp2(sacc[mt][nt][2] - mn1);
                sacc[mt][nt][3] = fexp2(sacc[mt][nt][3] - mn1);
                s0 += sacc[mt][nt][0] + sacc[mt][nt][1];
                s1 += sacc[mt][nt][2] + sacc[mt][nt][3];
            }
            s0 += __shfl_xor_sync(0xffffffffu, s0, 1);
            s0 += __shfl_xor_sync(0xffffffffu, s0, 2);
            s1 += __shfl_xor_sync(0xffffffffu, s1, 1);
            s1 += __shfl_xor_sync(0xffffffffu, s1, 2);
            lrow[mt][0] = lrow[mt][0] * corr0 + s0;  mrow[mt][0] = mn0;
            lrow[mt][1] = lrow[mt][1] * corr1 + s1;  mrow[mt][1] = mn1;
#pragma unroll
            for (int nt = 0; nt < 8; nt++) {
                oacc[mt][nt][0] *= corr0; oacc[mt][nt][1] *= corr0;
                oacc[mt][nt][2] *= corr1; oacc[mt][nt][3] *= corr1;
            }

            // Stage P (tf32-rounded) into this warp's private rows of Ps.
#pragma unroll
            for (int nt = 0; nt < 8; nt++) {
                float2 v0 = make_float2(f2tf32f(sacc[mt][nt][0]), f2tf32f(sacc[mt][nt][1]));
                float2 v1 = make_float2(f2tf32f(sacc[mt][nt][2]), f2tf32f(sacc[mt][nt][3]));
                *(float2*)&Ps[wm + mt * 16 + gid][nt * 8 + tig * 2] = v0;
                *(float2*)&Ps[wm + mt * 16 + gid + 8][nt * 8 + tig * 2] = v1;
            }
        }
        __syncwarp();

        // Prefetch next tile now (sacc dead; overlaps PV compute).
        if (kt + 1 < ntile) {
            const float* Kn = Kb + (size_t)(kt + 1) * AKV * EMB;
            const float* Vn = Vb + (size_t)(kt + 1) * AKV * EMB;
#pragma unroll
            for (int p = 0; p < 8; p++) {
                int idx = tid + p * 128;
                int row = idx >> 4;
                int c4  = (idx & 15) * 4;
                pk[p] = *(const float4*)(Kn + (size_t)row * EMB + c4);
                pv[p] = *(const float4*)(Vn + (size_t)row * EMB + c4);
            }
        }

        // O += P V : A = Ps rows (q), B = V^T via transposed reads of Vs.
#pragma unroll
        for (int ks = 0; ks < 8; ks++) {
            const int kb = ks * 8;
            uint32_t a[2][4];
#pragma unroll
            for (int mt = 0; mt < 2; mt++) {
                const float* ap = &Ps[wm + mt * 16 + gid][kb + tig];
                a[mt][0] = __float_as_uint(ap[0]);
                a[mt][2] = __float_as_uint(ap[4]);
                const float* ap8 = &Ps[wm + mt * 16 + gid + 8][kb + tig];
                a[mt][1] = __float_as_uint(ap8[0]);
                a[mt][3] = __float_as_uint(ap8[4]);
            }
#pragma unroll
            for (int nt = 0; nt < 8; nt++) {
                uint32_t bf[2];
                bf[0] = __float_as_uint(Vs[kb + tig][nt * 8 + gid]);
                bf[1] = __float_as_uint(Vs[kb + tig + 4][nt * 8 + gid]);
                mma_tf32(oacc[0][nt], a[0], bf);
                mma_tf32(oacc[1][nt], a[1], bf);
            }
        }
    }

    // Epilogue: normalize and write.
#pragma unroll
    for (int mt = 0; mt < 2; mt++) {
        const float inv0 = 1.0f / lrow[mt][0], inv1 = 1.0f / lrow[mt][1];
        const int r0 = wm + mt * 16 + gid, r1 = r0 + 8;
#pragma unroll
        for (int nt = 0; nt < 8; nt++) {
            const int c = nt * 8 + tig * 2;
            float2 v0 = make_float2(oacc[mt][nt][0] * inv0, oacc[mt][nt][1] * inv0);
            float2 v1 = make_float2(oacc[mt][nt][2] * inv1, oacc[mt][nt][3] * inv1);
            *(float2*)(Ob + (size_t)r0 * EMB + c) = v0;
            *(float2*)(Ob + (size_t)r1 * EMB + c) = v1;
        }
    }
}

// ---------------------------------------------------------------------------
// Launch
// ---------------------------------------------------------------------------
extern "C" void kernel_launch(void* const* d_in, const int* in_sizes, int n_in,
                              void* d_out, int out_size)
{
    const float* query = (const float*)d_in[0];
    const float* key   = (const float*)d_in[1];
    const float* value = (const float*)d_in[2];
    const float* Wq    = (const float*)d_in[3];
    const float* bq    = (const float*)d_in[4];
    const float* Wk    = (const float*)d_in[5];
    const float* bk    = (const float*)d_in[6];
    const float* Wv    = (const float*)d_in[7];
    const float* bv    = (const float*)d_in[8];
    const float* Wo    = (const float*)d_in[9];
    const float* bo    = (const float*)d_in[10];
    float* out = (float*)d_out;

    float *pQ, *pK, *pV, *pA;
    cudaGetSymbolAddress((void**)&pQ, g_Q);
    cudaGetSymbolAddress((void**)&pK, g_K);
    cudaGetSymbolAddress((void**)&pV, g_V);
    cudaGetSymbolAddress((void**)&pA, g_A);

    cudaFuncSetAttribute(gemm_tf32_mma,
                         cudaFuncAttributeMaxDynamicSharedMemorySize,
                         GEMM_SMEM_BYTES);
    cudaFuncSetAttribute(flash_attn_mma,
                         cudaFuncAttributeMaxDynamicSharedMemorySize,
                         ATTN_SMEM_BYTES);

    dim3 gblk(EMB / GBN, MROWS / GBM);   // (8, 32)

    gemm_tf32_mma<<<gblk, 256, GEMM_SMEM_BYTES>>>(query, Wq, bq, pQ, MROWS, EMB, EMB);
    gemm_tf32_mma<<<gblk, 256, GEMM_SMEM_BYTES>>>(key,   Wk, bk, pK, MROWS, EMB, EMB);
    gemm_tf32_mma<<<gblk, 256, GEMM_SMEM_BYTES>>>(value, Wv, bv, pV, MROWS, EMB, EMB);

    dim3 gattn(SEQ / AQ, NHEAD, BATCH);  // (16, 16, 2)
    flash_attn_mma<<<gattn, 128, ATTN_SMEM_BYTES>>>();

    gemm_tf32_mma<<<gblk, 256, GEMM_SMEM_BYTES>>>(pA, Wo, bo, out, MROWS, EMB, EMB);
}

// round 6
// speedup vs baseline: 3.1453x; 1.0398x over previous
#include <cuda_runtime.h>
#include <cuda_bf16.h>
#include <math.h>
#include <stdint.h>

// Problem constants
#define BATCH 2
#define SEQ   2048
#define EMB   1024
#define NHEAD 16
#define HDIM  64
#define MROWS (BATCH*SEQ)   // 4096

// ---------------------------------------------------------------------------
// Scratch (device globals; no runtime allocation allowed)
// ---------------------------------------------------------------------------
__device__ float g_Q[MROWS * EMB];
__device__ float g_K[MROWS * EMB];
__device__ float g_V[MROWS * EMB];
__device__ float g_A[MROWS * EMB];

// ---------------------------------------------------------------------------
// Helpers
// ---------------------------------------------------------------------------
__device__ __forceinline__ uint32_t smem_u32(const void* p) {
    uint32_t a;
    asm("{ .reg .u64 t; cvta.to.shared.u64 t, %1; cvt.u32.u64 %0, t; }"
        : "=r"(a) : "l"(p));
    return a;
}
__device__ __forceinline__ uint32_t f2tf32(float x) {
    uint32_t r;
    asm("cvt.rna.tf32.f32 %0, %1;" : "=r"(r) : "f"(x));
    return r;
}
__device__ __forceinline__ float fexp2(float x) {
    float r;
    asm("ex2.approx.ftz.f32 %0, %1;" : "=f"(r) : "f"(x));
    return r;
}
__device__ __forceinline__ void mma_tf32(float* c, const uint32_t* a, const uint32_t* b) {
    asm volatile(
        "mma.sync.aligned.m16n8k8.row.col.f32.tf32.tf32.f32 "
        "{%0,%1,%2,%3}, {%4,%5,%6,%7}, {%8,%9}, {%0,%1,%2,%3};"
        : "+f"(c[0]), "+f"(c[1]), "+f"(c[2]), "+f"(c[3])
        : "r"(a[0]), "r"(a[1]), "r"(a[2]), "r"(a[3]), "r"(b[0]), "r"(b[1]));
}

#define CP_ASYNC16(dst_u32, src_ptr) \
    asm volatile("cp.async.cg.shared.global [%0], [%1], 16;" \
                 :: "r"(dst_u32), "l"(src_ptr))
#define CP_COMMIT() asm volatile("cp.async.commit_group;")
#define CP_WAIT(n)  asm volatile("cp.async.wait_group %0;" :: "n"(n))

// ---------------------------------------------------------------------------
// tf32 tensor-core GEMM: C[M,N] = A[M,K] @ W[N,K]^T + bias[N]
// 128x128x32 block, 256 threads, 3-stage cp.async pipeline.
// Raw fp32 in smem; cvt.rna at fragment read.
// ---------------------------------------------------------------------------
#define GBM 128
#define GBN 128
#define GBK 32
#define PADK 36
#define GSTG_FLTS (2 * GBM * PADK)                  // A+B per stage = 9216
#define GEMM_SMEM_BYTES (3 * GSTG_FLTS * 4)         // 110592

__global__ __launch_bounds__(256) void gemm_tf32_mma(
    const float* __restrict__ A,     // [M,K]
    const float* __restrict__ W,     // [N,K]
    const float* __restrict__ bias,  // [N]
    float* __restrict__ C,           // [M,N]
    int M, int N, int K)
{
    extern __shared__ float smem[];

    const int tid  = threadIdx.x;
    const int lane = tid & 31;
    const int warp = tid >> 5;
    const int bm = blockIdx.y * GBM;
    const int bn = blockIdx.x * GBN;

    const int wm = (warp >> 2) * 64;
    const int wn = (warp & 3) * 32;
    const int gid = lane >> 2;
    const int tig = lane & 3;

    float acc[4][4][4];
#pragma unroll
    for (int mt = 0; mt < 4; mt++)
#pragma unroll
        for (int nt = 0; nt < 4; nt++)
#pragma unroll
            for (int r = 0; r < 4; r++) acc[mt][nt][r] = 0.f;

    // async loader: stage s gets A[.,k0:k0+32], W[.,k0:k0+32] raw fp32
    auto load_stage = [&](int s, int k0) {
        float* As = smem + s * GSTG_FLTS;
        float* Bs = As + GBM * PADK;
#pragma unroll
        for (int p = 0; p < 4; p++) {
            int idx = tid + p * 256;       // 0..1023
            int row = idx >> 3;            // 0..127
            int c   = (idx & 7) * 4;       // 0..28
            CP_ASYNC16(smem_u32(As + row * PADK + c),
                       A + (size_t)(bm + row) * K + k0 + c);
            CP_ASYNC16(smem_u32(Bs + row * PADK + c),
                       W + (size_t)(bn + row) * K + k0 + c);
        }
        CP_COMMIT();
    };

    const int nchunk = K / GBK;   // 32
    load_stage(0, 0);
    load_stage(1, GBK);

    for (int i = 0; i < nchunk; i++) {
        CP_WAIT(1);
        __syncthreads();
        if (i + 2 < nchunk) load_stage((i + 2) % 3, (i + 2) * GBK);

        const float* As = smem + (i % 3) * GSTG_FLTS;
        const float* Bs = As + GBM * PADK;

#pragma unroll
        for (int ks = 0; ks < 4; ks++) {
            const int kb = ks * 8;
            uint32_t afr[4][4], bfr[4][2];
#pragma unroll
            for (int mt = 0; mt < 4; mt++) {
                const float* p = As + (wm + mt * 16 + gid) * PADK + kb + tig;
                afr[mt][0] = f2tf32(p[0]);
                afr[mt][2] = f2tf32(p[4]);
                const float* p8 = p + 8 * PADK;
                afr[mt][1] = f2tf32(p8[0]);
                afr[mt][3] = f2tf32(p8[4]);
            }
#pragma unroll
            for (int nt = 0; nt < 4; nt++) {
                const float* q = Bs + (wn + nt * 8 + gid) * PADK + kb + tig;
                bfr[nt][0] = f2tf32(q[0]);
                bfr[nt][1] = f2tf32(q[4]);
            }
#pragma unroll
            for (int mt = 0; mt < 4; mt++)
#pragma unroll
                for (int nt = 0; nt < 4; nt++)
                    mma_tf32(acc[mt][nt], afr[mt], bfr[nt]);
        }
        __syncthreads();
    }

#pragma unroll
    for (int nt = 0; nt < 4; nt++) {
        const int c0 = bn + wn + nt * 8 + tig * 2;
        const float b0 = bias[c0], b1 = bias[c0 + 1];
#pragma unroll
        for (int mt = 0; mt < 4; mt++) {
            const int r0 = bm + wm + mt * 16 + gid;
            float2 v0 = make_float2(acc[mt][nt][0] + b0, acc[mt][nt][1] + b1);
            float2 v1 = make_float2(acc[mt][nt][2] + b0, acc[mt][nt][3] + b1);
            *(float2*)(C + (size_t)r0 * N + c0) = v0;
            *(float2*)(C + (size_t)(r0 + 8) * N + c0) = v1;
        }
    }
}

// ---------------------------------------------------------------------------
// Flash attention, mma.sync tf32, v3: cp.async double-buffered K/V.
// CTA: 128 q rows, 128 threads, 4 warps (32 q rows each, mt=2).
// smem: R0 (Q staging, later KV stage B), R1 (KV stage A), Ps.
// Raw fp32 in smem; cvt.rna at fragment read. P staged tf32 in smem.
// ---------------------------------------------------------------------------
#define AQ   128
#define AKV  64
#define APAD 68
#define AREG_FLTS (AQ * APAD)          // 8704 floats per region
#define ATTN_SMEM_BYTES (3 * AREG_FLTS * 4)   // 104448

__global__ __launch_bounds__(128, 2) void flash_attn_mma()
{
    extern __shared__ float dsm[];
    float* R0 = dsm;                    // Q staging -> KV slot for odd tiles
    float* R1 = dsm + AREG_FLTS;        // KV slot for even tiles
    float (*Ps)[APAD] = (float(*)[APAD])(dsm + 2 * AREG_FLTS);

    const int qt = blockIdx.x;
    const int h  = blockIdx.y;
    const int b  = blockIdx.z;

    const float* Qb = g_Q + ((size_t)b * SEQ + qt * AQ) * EMB + h * HDIM;
    const float* Kb = g_K + (size_t)b * SEQ * EMB + h * HDIM;
    const float* Vb = g_V + (size_t)b * SEQ * EMB + h * HDIM;
    float*       Ob = g_A + ((size_t)b * SEQ + qt * AQ) * EMB + h * HDIM;

    const int tid  = threadIdx.x;
    const int lane = tid & 31;
    const int warp = tid >> 5;
    const int gid  = lane >> 2;
    const int tig  = lane & 3;
    const int wm   = warp * 32;

    // async KV loader into region base: K rows [0,64), V rows [64,128)
    auto load_kv = [&](float* base, int kt) {
        const float* Kt = Kb + (size_t)kt * AKV * EMB;
        const float* Vt = Vb + (size_t)kt * AKV * EMB;
#pragma unroll
        for (int p = 0; p < 8; p++) {
            int idx = tid + p * 128;       // 0..1023
            int row = idx >> 4;            // 0..63
            int c   = (idx & 15) * 4;      // 0..60
            CP_ASYNC16(smem_u32(base + row * APAD + c),
                       Kt + (size_t)row * EMB + c);
            CP_ASYNC16(smem_u32(base + (AKV + row) * APAD + c),
                       Vt + (size_t)row * EMB + c);
        }
        CP_COMMIT();
    };

    // Prologue: Q -> R0 (async), KV0 -> R1 (async).
#pragma unroll
    for (int p = 0; p < 16; p++) {
        int idx = tid + p * 128;       // 0..2047
        int row = idx >> 4;            // 0..127
        int c   = (idx & 15) * 4;
        CP_ASYNC16(smem_u32(R0 + row * APAD + c),
                   Qb + (size_t)row * EMB + c);
    }
    CP_COMMIT();
    load_kv(R1, 0);

    CP_WAIT(1);            // Q ready
    __syncthreads();

    // Hoist Q fragments: apply softmax scale * log2(e), round to tf32.
    const float qscale = 0.125f * 1.4426950408889634f;
    uint32_t qfr[2][8][4];
#pragma unroll
    for (int mt = 0; mt < 2; mt++)
#pragma unroll
        for (int ks = 0; ks < 8; ks++) {
            const float* ap = R0 + (wm + mt * 16 + gid) * APAD + ks * 8 + tig;
            qfr[mt][ks][0] = f2tf32(ap[0] * qscale);
            qfr[mt][ks][2] = f2tf32(ap[4] * qscale);
            const float* ap8 = ap + 8 * APAD;
            qfr[mt][ks][1] = f2tf32(ap8[0] * qscale);
            qfr[mt][ks][3] = f2tf32(ap8[4] * qscale);
        }
    __syncthreads();       // all warps done reading R0
    load_kv(R0, 1);        // KV1 -> R0

    float oacc[2][8][4];
#pragma unroll
    for (int mt = 0; mt < 2; mt++)
#pragma unroll
        for (int nt = 0; nt < 8; nt++)
#pragma unroll
            for (int r = 0; r < 4; r++) oacc[mt][nt][r] = 0.f;
    float mrow[2][2], lrow[2][2];
#pragma unroll
    for (int mt = 0; mt < 2; mt++) {
        mrow[mt][0] = -1e30f; mrow[mt][1] = -1e30f;
        lrow[mt][0] = 0.f;    lrow[mt][1] = 0.f;
    }

    const int ntile = SEQ / AKV;   // 32
    for (int kt = 0; kt < ntile; kt++) {
        CP_WAIT(1);        // KV_kt resident
        __syncthreads();

        float* slot = (kt & 1) ? R0 : R1;
        float (*Ks)[APAD] = (float(*)[APAD])slot;
        float (*Vs)[APAD] = (float(*)[APAD])(slot + AKV * APAD);

        // S = Q K^T for this warp's 32 rows x 64 keys.
        float sacc[2][8][4];
#pragma unroll
        for (int mt = 0; mt < 2; mt++)
#pragma unroll
            for (int nt = 0; nt < 8; nt++)
#pragma unroll
                for (int r = 0; r < 4; r++) sacc[mt][nt][r] = 0.f;

#pragma unroll
        for (int ks = 0; ks < 8; ks++) {
            const int kb = ks * 8;
#pragma unroll
            for (int nt = 0; nt < 8; nt++) {
                uint32_t bf[2];
                const float* bp = &Ks[nt * 8 + gid][kb + tig];
                bf[0] = f2tf32(bp[0]);
                bf[1] = f2tf32(bp[4]);
                mma_tf32(sacc[0][nt], qfr[0][ks], bf);
                mma_tf32(sacc[1][nt], qfr[1][ks], bf);
            }
        }

        // Online softmax (exp2 domain) per mt row-pair.
#pragma unroll
        for (int mt = 0; mt < 2; mt++) {
            float mx0 = -1e30f, mx1 = -1e30f;
#pragma unroll
            for (int nt = 0; nt < 8; nt++) {
                mx0 = fmaxf(mx0, fmaxf(sacc[mt][nt][0], sacc[mt][nt][1]));
                mx1 = fmaxf(mx1, fmaxf(sacc[mt][nt][2], sacc[mt][nt][3]));
            }
            mx0 = fmaxf(mx0, __shfl_xor_sync(0xffffffffu, mx0, 1));
            mx0 = fmaxf(mx0, __shfl_xor_sync(0xffffffffu, mx0, 2));
            mx1 = fmaxf(mx1, __shfl_xor_sync(0xffffffffu, mx1, 1));
            mx1 = fmaxf(mx1, __shfl_xor_sync(0xffffffffu, mx1, 2));

            float mn0 = fmaxf(mrow[mt][0], mx0), mn1 = fmaxf(mrow[mt][1], mx1);
            float corr0 = fexp2(mrow[mt][0] - mn0), corr1 = fexp2(mrow[mt][1] - mn1);
            float s0 = 0.f, s1 = 0.f;
#pragma unroll
            for (int nt = 0; nt < 8; nt++) {
                sacc[mt][nt][0] = fexp2(sacc[mt][nt][0] - mn0);
                sacc[mt][nt][1] = fexp2(sacc[mt][nt][1] - mn0);
                sacc[mt][nt][2] = fexp2(sacc[mt][nt][2] - mn1);
                sacc[mt][nt][3] = fexp2(sacc[mt][nt][3] - mn1);
                s0 += sacc[mt][nt][0] + sacc[mt][nt][1];
                s1 += sacc[mt][nt][2] + sacc[mt][nt][3];
            }
            s0 += __shfl_xor_sync(0xffffffffu, s0, 1);
            s0 += __shfl_xor_sync(0xffffffffu, s0, 2);
            s1 += __shfl_xor_sync(0xffffffffu, s1, 1);
            s1 += __shfl_xor_sync(0xffffffffu, s1, 2);
            lrow[mt][0] = lrow[mt][0] * corr0 + s0;  mrow[mt][0] = mn0;
            lrow[mt][1] = lrow[mt][1] * corr1 + s1;  mrow[mt][1] = mn1;
#pragma unroll
            for (int nt = 0; nt < 8; nt++) {
                oacc[mt][nt][0] *= corr0; oacc[mt][nt][1] *= corr0;
                oacc[mt][nt][2] *= corr1; oacc[mt][nt][3] *= corr1;
            }

            // Stage P (tf32-rounded) into this warp's private rows of Ps.
#pragma unroll
            for (int nt = 0; nt < 8; nt++) {
                float2 v0 = make_float2(
                    __uint_as_float(f2tf32(sacc[mt][nt][0])),
                    __uint_as_float(f2tf32(sacc[mt][nt][1])));
                float2 v1 = make_float2(
                    __uint_as_float(f2tf32(sacc[mt][nt][2])),
                    __uint_as_float(f2tf32(sacc[mt][nt][3])));
                *(float2*)&Ps[wm + mt * 16 + gid][nt * 8 + tig * 2] = v0;
                *(float2*)&Ps[wm + mt * 16 + gid + 8][nt * 8 + tig * 2] = v1;
            }
        }
        __syncwarp();

        // O += P V : A = Ps rows (q), B = V^T via transposed reads of Vs.
#pragma unroll
        for (int ks = 0; ks < 8; ks++) {
            const int kb = ks * 8;
            uint32_t a[2][4];
#pragma unroll
            for (int mt = 0; mt < 2; mt++) {
                const float* ap = &Ps[wm + mt * 16 + gid][kb + tig];
                a[mt][0] = __float_as_uint(ap[0]);
                a[mt][2] = __float_as_uint(ap[4]);
                const float* ap8 = &Ps[wm + mt * 16 + gid + 8][kb + tig];
                a[mt][1] = __float_as_uint(ap8[0]);
                a[mt][3] = __float_as_uint(ap8[4]);
            }
#pragma unroll
            for (int nt = 0; nt < 8; nt++) {
                uint32_t bf[2];
                bf[0] = f2tf32(Vs[kb + tig][nt * 8 + gid]);
                bf[1] = f2tf32(Vs[kb + tig + 4][nt * 8 + gid]);
                mma_tf32(oacc[0][nt], a[0], bf);
                mma_tf32(oacc[1][nt], a[1], bf);
            }
        }

        __syncthreads();   // all warps done reading this slot
        if (kt + 2 < ntile) load_kv(slot, kt + 2);
    }

    // Epilogue: normalize and write.
#pragma unroll
    for (int mt = 0; mt < 2; mt++) {
        const float inv0 = 1.0f / lrow[mt][0], inv1 = 1.0f / lrow[mt][1];
        const int r0 = wm + mt * 16 + gid, r1 = r0 + 8;
#pragma unroll
        for (int nt = 0; nt < 8; nt++) {
            const int c = nt * 8 + tig * 2;
            float2 v0 = make_float2(oacc[mt][nt][0] * inv0, oacc[mt][nt][1] * inv0);
            float2 v1 = make_float2(oacc[mt][nt][2] * inv1, oacc[mt][nt][3] * inv1);
            *(float2*)(Ob + (size_t)r0 * EMB + c) = v0;
            *(float2*)(Ob + (size_t)r1 * EMB + c) = v1;
        }
    }
}

// ---------------------------------------------------------------------------
// Launch
// ---------------------------------------------------------------------------
extern "C" void kernel_launch(void* const* d_in, const int* in_sizes, int n_in,
                              void* d_out, int out_size)
{
    const float* query = (const float*)d_in[0];
    const float* key   = (const float*)d_in[1];
    const float* value = (const float*)d_in[2];
    const float* Wq    = (const float*)d_in[3];
    const float* bq    = (const float*)d_in[4];
    const float* Wk    = (const float*)d_in[5];
    const float* bk    = (const float*)d_in[6];
    const float* Wv    = (const float*)d_in[7];
    const float* bv    = (const float*)d_in[8];
    const float* Wo    = (const float*)d_in[9];
    const float* bo    = (const float*)d_in[10];
    float* out = (float*)d_out;

    float *pQ, *pK, *pV, *pA;
    cudaGetSymbolAddress((void**)&pQ, g_Q);
    cudaGetSymbolAddress((void**)&pK, g_K);
    cudaGetSymbolAddress((void**)&pV, g_V);
    cudaGetSymbolAddress((void**)&pA, g_A);

    cudaFuncSetAttribute(gemm_tf32_mma,
                         cudaFuncAttributeMaxDynamicSharedMemorySize,
                         GEMM_SMEM_BYTES);
    cudaFuncSetAttribute(flash_attn_mma,
                         cudaFuncAttributeMaxDynamicSharedMemorySize,
                         ATTN_SMEM_BYTES);

    dim3 gblk(EMB / GBN, MROWS / GBM);   // (8, 32)

    gemm_tf32_mma<<<gblk, 256, GEMM_SMEM_BYTES>>>(query, Wq, bq, pQ, MROWS, EMB, EMB);
    gemm_tf32_mma<<<gblk, 256, GEMM_SMEM_BYTES>>>(key,   Wk, bk, pK, MROWS, EMB, EMB);
    gemm_tf32_mma<<<gblk, 256, GEMM_SMEM_BYTES>>>(value, Wv, bv, pV, MROWS, EMB, EMB);

    dim3 gattn(SEQ / AQ, NHEAD, BATCH);  // (16, 16, 2)
    flash_attn_mma<<<gattn, 128, ATTN_SMEM_BYTES>>>();

    gemm_tf32_mma<<<gblk, 256, GEMM_SMEM_BYTES>>>(pA, Wo, bo, out, MROWS, EMB, EMB);
}

// round 7
// speedup vs baseline: 3.4910x; 1.1099x over previous
#include <cuda_runtime.h>
#include <cuda_bf16.h>
#include <math.h>
#include <stdint.h>

// Problem constants
#define BATCH 2
#define SEQ   2048
#define EMB   1024
#define NHEAD 16
#define HDIM  64
#define MROWS (BATCH*SEQ)   // 4096

// ---------------------------------------------------------------------------
// Scratch (device globals; no runtime allocation allowed)
// ---------------------------------------------------------------------------
__device__ float g_Q[MROWS * EMB];
__device__ float g_K[MROWS * EMB];
__device__ float g_V[MROWS * EMB];
__device__ float g_A[MROWS * EMB];
// tf32-pre-rounded copies of inputs and weights
__device__ float g_QR[MROWS * EMB];
__device__ float g_KR[MROWS * EMB];
__device__ float g_VR[MROWS * EMB];
__device__ float g_WQ[EMB * EMB];
__device__ float g_WK[EMB * EMB];
__device__ float g_WV[EMB * EMB];
__device__ float g_WO[EMB * EMB];

// ---------------------------------------------------------------------------
// Helpers
// ---------------------------------------------------------------------------
__device__ __forceinline__ uint32_t smem_u32(const void* p) {
    uint32_t a;
    asm("{ .reg .u64 t; cvta.to.shared.u64 t, %1; cvt.u32.u64 %0, t; }"
        : "=r"(a) : "l"(p));
    return a;
}
__device__ __forceinline__ uint32_t f2tf32(float x) {
    uint32_t r;
    asm("cvt.rna.tf32.f32 %0, %1;" : "=r"(r) : "f"(x));
    return r;
}
__device__ __forceinline__ float f2tf32f(float x) {
    return __uint_as_float(f2tf32(x));
}
__device__ __forceinline__ float fexp2(float x) {
    float r;
    asm("ex2.approx.ftz.f32 %0, %1;" : "=f"(r) : "f"(x));
    return r;
}
__device__ __forceinline__ void mma_tf32(float* c, const uint32_t* a, const uint32_t* b) {
    asm volatile(
        "mma.sync.aligned.m16n8k8.row.col.f32.tf32.tf32.f32 "
        "{%0,%1,%2,%3}, {%4,%5,%6,%7}, {%8,%9}, {%0,%1,%2,%3};"
        : "+f"(c[0]), "+f"(c[1]), "+f"(c[2]), "+f"(c[3])
        : "r"(a[0]), "r"(a[1]), "r"(a[2]), "r"(a[3]), "r"(b[0]), "r"(b[1]));
}

#define CP_ASYNC16(dst_u32, src_ptr) \
    asm volatile("cp.async.cg.shared.global [%0], [%1], 16;" \
                 :: "r"(dst_u32), "l"(src_ptr))
#define CP_COMMIT() asm volatile("cp.async.commit_group;")
#define CP_WAIT(n)  asm volatile("cp.async.wait_group %0;" :: "n"(n))

// ---------------------------------------------------------------------------
// Prologue: round tensors to tf32 (rna) into scratch. blockIdx.y picks tensor.
// ---------------------------------------------------------------------------
__global__ __launch_bounds__(256) void round_tf32_all(
    const float* q, const float* k, const float* v,
    const float* wq, const float* wk, const float* wv, const float* wo)
{
    const float* src; float* dst; int n;
    switch (blockIdx.y) {
        case 0: src = q;  dst = g_QR; n = MROWS * EMB; break;
        case 1: src = k;  dst = g_KR; n = MROWS * EMB; break;
        case 2: src = v;  dst = g_VR; n = MROWS * EMB; break;
        case 3: src = wq; dst = g_WQ; n = EMB * EMB;   break;
        case 4: src = wk; dst = g_WK; n = EMB * EMB;   break;
        case 5: src = wv; dst = g_WV; n = EMB * EMB;   break;
        default: src = wo; dst = g_WO; n = EMB * EMB;  break;
    }
    int n4 = n >> 2;
    for (int i = blockIdx.x * blockDim.x + threadIdx.x; i < n4;
         i += gridDim.x * blockDim.x) {
        float4 x = ((const float4*)src)[i];
        float4 y;
        y.x = f2tf32f(x.x); y.y = f2tf32f(x.y);
        y.z = f2tf32f(x.z); y.w = f2tf32f(x.w);
        ((float4*)dst)[i] = y;
    }
}

// ---------------------------------------------------------------------------
// tf32 tensor-core GEMM: C[M,N] = A[M,K] @ W[N,K]^T + bias[N]
// A and W are tf32-pre-rounded; no cvt in hot loop.
// round_c: round C to tf32 at store (for tensors feeding another mma).
// ---------------------------------------------------------------------------
#define GBM 128
#define GBN 128
#define GBK 32
#define PADK 36
#define GSTG_FLTS (2 * GBM * PADK)
#define GEMM_SMEM_BYTES (3 * GSTG_FLTS * 4)         // 110592

__global__ __launch_bounds__(256) void gemm_tf32_mma(
    const float* __restrict__ A,     // [M,K] tf32-rounded
    const float* __restrict__ W,     // [N,K] tf32-rounded
    const float* __restrict__ bias,  // [N] fp32
    float* __restrict__ C,           // [M,N]
    int M, int N, int K, int round_c)
{
    extern __shared__ float smem[];

    const int tid  = threadIdx.x;
    const int lane = tid & 31;
    const int warp = tid >> 5;
    const int bm = blockIdx.y * GBM;
    const int bn = blockIdx.x * GBN;

    const int wm = (warp >> 2) * 64;
    const int wn = (warp & 3) * 32;
    const int gid = lane >> 2;
    const int tig = lane & 3;

    float acc[4][4][4];
#pragma unroll
    for (int mt = 0; mt < 4; mt++)
#pragma unroll
        for (int nt = 0; nt < 4; nt++)
#pragma unroll
            for (int r = 0; r < 4; r++) acc[mt][nt][r] = 0.f;

    auto load_stage = [&](int s, int k0) {
        float* As = smem + s * GSTG_FLTS;
        float* Bs = As + GBM * PADK;
#pragma unroll
        for (int p = 0; p < 4; p++) {
            int idx = tid + p * 256;
            int row = idx >> 3;
            int c   = (idx & 7) * 4;
            CP_ASYNC16(smem_u32(As + row * PADK + c),
                       A + (size_t)(bm + row) * K + k0 + c);
            CP_ASYNC16(smem_u32(Bs + row * PADK + c),
                       W + (size_t)(bn + row) * K + k0 + c);
        }
        CP_COMMIT();
    };

    const int nchunk = K / GBK;
    load_stage(0, 0);
    load_stage(1, GBK);

    for (int i = 0; i < nchunk; i++) {
        CP_WAIT(1);
        __syncthreads();
        if (i + 2 < nchunk) load_stage((i + 2) % 3, (i + 2) * GBK);

        const float* As = smem + (i % 3) * GSTG_FLTS;
        const float* Bs = As + GBM * PADK;

#pragma unroll
        for (int ks = 0; ks < 4; ks++) {
            const int kb = ks * 8;
            uint32_t afr[4][4], bfr[4][2];
#pragma unroll
            for (int mt = 0; mt < 4; mt++) {
                const float* p = As + (wm + mt * 16 + gid) * PADK + kb + tig;
                afr[mt][0] = __float_as_uint(p[0]);
                afr[mt][2] = __float_as_uint(p[4]);
                const float* p8 = p + 8 * PADK;
                afr[mt][1] = __float_as_uint(p8[0]);
                afr[mt][3] = __float_as_uint(p8[4]);
            }
#pragma unroll
            for (int nt = 0; nt < 4; nt++) {
                const float* q = Bs + (wn + nt * 8 + gid) * PADK + kb + tig;
                bfr[nt][0] = __float_as_uint(q[0]);
                bfr[nt][1] = __float_as_uint(q[4]);
            }
#pragma unroll
            for (int mt = 0; mt < 4; mt++)
#pragma unroll
                for (int nt = 0; nt < 4; nt++)
                    mma_tf32(acc[mt][nt], afr[mt], bfr[nt]);
        }
        __syncthreads();
    }

#pragma unroll
    for (int nt = 0; nt < 4; nt++) {
        const int c0 = bn + wn + nt * 8 + tig * 2;
        const float b0 = bias[c0], b1 = bias[c0 + 1];
#pragma unroll
        for (int mt = 0; mt < 4; mt++) {
            const int r0 = bm + wm + mt * 16 + gid;
            float2 v0 = make_float2(acc[mt][nt][0] + b0, acc[mt][nt][1] + b1);
            float2 v1 = make_float2(acc[mt][nt][2] + b0, acc[mt][nt][3] + b1);
            if (round_c) {
                v0.x = f2tf32f(v0.x); v0.y = f2tf32f(v0.y);
                v1.x = f2tf32f(v1.x); v1.y = f2tf32f(v1.y);
            }
            *(float2*)(C + (size_t)r0 * N + c0) = v0;
            *(float2*)(C + (size_t)(r0 + 8) * N + c0) = v1;
        }
    }
}

// ---------------------------------------------------------------------------
// Flash attention, mma.sync tf32, v4: cp.async double-buffered K/V.
// Q/K/V arrive tf32-pre-rounded -> no cvt on K/V fragment reads.
// CTA: 128 q rows, 128 threads, 4 warps (32 q rows each, mt=2).
// ---------------------------------------------------------------------------
#define AQ   128
#define AKV  64
#define APAD 68
#define AREG_FLTS (AQ * APAD)
#define ATTN_SMEM_BYTES (3 * AREG_FLTS * 4)   // 104448

__global__ __launch_bounds__(128, 2) void flash_attn_mma()
{
    extern __shared__ float dsm[];
    float* R0 = dsm;                    // Q staging -> KV slot for odd tiles
    float* R1 = dsm + AREG_FLTS;        // KV slot for even tiles
    float (*Ps)[APAD] = (float(*)[APAD])(dsm + 2 * AREG_FLTS);

    const int qt = blockIdx.x;
    const int h  = blockIdx.y;
    const int b  = blockIdx.z;

    const float* Qb = g_Q + ((size_t)b * SEQ + qt * AQ) * EMB + h * HDIM;
    const float* Kb = g_K + (size_t)b * SEQ * EMB + h * HDIM;
    const float* Vb = g_V + (size_t)b * SEQ * EMB + h * HDIM;
    float*       Ob = g_A + ((size_t)b * SEQ + qt * AQ) * EMB + h * HDIM;

    const int tid  = threadIdx.x;
    const int lane = tid & 31;
    const int warp = tid >> 5;
    const int gid  = lane >> 2;
    const int tig  = lane & 3;
    const int wm   = warp * 32;

    auto load_kv = [&](float* base, int kt) {
        const float* Kt = Kb + (size_t)kt * AKV * EMB;
        const float* Vt = Vb + (size_t)kt * AKV * EMB;
#pragma unroll
        for (int p = 0; p < 8; p++) {
            int idx = tid + p * 128;
            int row = idx >> 4;
            int c   = (idx & 15) * 4;
            CP_ASYNC16(smem_u32(base + row * APAD + c),
                       Kt + (size_t)row * EMB + c);
            CP_ASYNC16(smem_u32(base + (AKV + row) * APAD + c),
                       Vt + (size_t)row * EMB + c);
        }
        CP_COMMIT();
    };

    // Prologue: Q -> R0 (async), KV0 -> R1 (async).
#pragma unroll
    for (int p = 0; p < 16; p++) {
        int idx = tid + p * 128;
        int row = idx >> 4;
        int c   = (idx & 15) * 4;
        CP_ASYNC16(smem_u32(R0 + row * APAD + c),
                   Qb + (size_t)row * EMB + c);
    }
    CP_COMMIT();
    load_kv(R1, 0);

    CP_WAIT(1);
    __syncthreads();

    // Hoist Q fragments: apply softmax scale * log2(e), re-round to tf32.
    const float qscale = 0.125f * 1.4426950408889634f;
    uint32_t qfr[2][8][4];
#pragma unroll
    for (int mt = 0; mt < 2; mt++)
#pragma unroll
        for (int ks = 0; ks < 8; ks++) {
            const float* ap = R0 + (wm + mt * 16 + gid) * APAD + ks * 8 + tig;
            qfr[mt][ks][0] = f2tf32(ap[0] * qscale);
            qfr[mt][ks][2] = f2tf32(ap[4] * qscale);
            const float* ap8 = ap + 8 * APAD;
            qfr[mt][ks][1] = f2tf32(ap8[0] * qscale);
            qfr[mt][ks][3] = f2tf32(ap8[4] * qscale);
        }
    __syncthreads();
    load_kv(R0, 1);

    float oacc[2][8][4];
#pragma unroll
    for (int mt = 0; mt < 2; mt++)
#pragma unroll
        for (int nt = 0; nt < 8; nt++)
#pragma unroll
            for (int r = 0; r < 4; r++) oacc[mt][nt][r] = 0.f;
    float mrow[2][2], lrow[2][2];
#pragma unroll
    for (int mt = 0; mt < 2; mt++) {
        mrow[mt][0] = -1e30f; mrow[mt][1] = -1e30f;
        lrow[mt][0] = 0.f;    lrow[mt][1] = 0.f;
    }

    const int ntile = SEQ / AKV;   // 32
    for (int kt = 0; kt < ntile; kt++) {
        CP_WAIT(1);
        __syncthreads();

        float* slot = (kt & 1) ? R0 : R1;
        float (*Ks)[APAD] = (float(*)[APAD])slot;
        float (*Vs)[APAD] = (float(*)[APAD])(slot + AKV * APAD);

        // S = Q K^T (K already tf32 -> raw fragment reads).
        float sacc[2][8][4];
#pragma unroll
        for (int mt = 0; mt < 2; mt++)
#pragma unroll
            for (int nt = 0; nt < 8; nt++)
#pragma unroll
                for (int r = 0; r < 4; r++) sacc[mt][nt][r] = 0.f;

#pragma unroll
        for (int ks = 0; ks < 8; ks++) {
            const int kb = ks * 8;
#pragma unroll
            for (int nt = 0; nt < 8; nt++) {
                uint32_t bf[2];
                const float* bp = &Ks[nt * 8 + gid][kb + tig];
                bf[0] = __float_as_uint(bp[0]);
                bf[1] = __float_as_uint(bp[4]);
                mma_tf32(sacc[0][nt], qfr[0][ks], bf);
                mma_tf32(sacc[1][nt], qfr[1][ks], bf);
            }
        }

        // Online softmax (exp2 domain).
#pragma unroll
        for (int mt = 0; mt < 2; mt++) {
            float mx0 = -1e30f, mx1 = -1e30f;
#pragma unroll
            for (int nt = 0; nt < 8; nt++) {
                mx0 = fmaxf(mx0, fmaxf(sacc[mt][nt][0], sacc[mt][nt][1]));
                mx1 = fmaxf(mx1, fmaxf(sacc[mt][nt][2], sacc[mt][nt][3]));
            }
            mx0 = fmaxf(mx0, __shfl_xor_sync(0xffffffffu, mx0, 1));
            mx0 = fmaxf(mx0, __shfl_xor_sync(0xffffffffu, mx0, 2));
            mx1 = fmaxf(mx1, __shfl_xor_sync(0xffffffffu, mx1, 1));
            mx1 = fmaxf(mx1, __shfl_xor_sync(0xffffffffu, mx1, 2));

            float mn0 = fmaxf(mrow[mt][0], mx0), mn1 = fmaxf(mrow[mt][1], mx1);
            float corr0 = fexp2(mrow[mt][0] - mn0), corr1 = fexp2(mrow[mt][1] - mn1);
            float s0 = 0.f, s1 = 0.f;
#pragma unroll
            for (int nt = 0; nt < 8; nt++) {
                sacc[mt][nt][0] = fexp2(sacc[mt][nt][0] - mn0);
                sacc[mt][nt][1] = fexp2(sacc[mt][nt][1] - mn0);
                sacc[mt][nt][2] = fexp2(sacc[mt][nt][2] - mn1);
                sacc[mt][nt][3] = fexp2(sacc[mt][nt][3] - mn1);
                s0 += sacc[mt][nt][0] + sacc[mt][nt][1];
                s1 += sacc[mt][nt][2] + sacc[mt][nt][3];
            }
            s0 += __shfl_xor_sync(0xffffffffu, s0, 1);
            s0 += __shfl_xor_sync(0xffffffffu, s0, 2);
            s1 += __shfl_xor_sync(0xffffffffu, s1, 1);
            s1 += __shfl_xor_sync(0xffffffffu, s1, 2);
            lrow[mt][0] = lrow[mt][0] * corr0 + s0;  mrow[mt][0] = mn0;
            lrow[mt][1] = lrow[mt][1] * corr1 + s1;  mrow[mt][1] = mn1;
#pragma unroll
            for (int nt = 0; nt < 8; nt++) {
                oacc[mt][nt][0] *= corr0; oacc[mt][nt][1] *= corr0;
                oacc[mt][nt][2] *= corr1; oacc[mt][nt][3] *= corr1;
            }

            // Stage P (tf32-rounded) into this warp's private rows of Ps.
#pragma unroll
            for (int nt = 0; nt < 8; nt++) {
                float2 v0 = make_float2(
                    __uint_as_float(f2tf32(sacc[mt][nt][0])),
                    __uint_as_float(f2tf32(sacc[mt][nt][1])));
                float2 v1 = make_float2(
                    __uint_as_float(f2tf32(sacc[mt][nt][2])),
                    __uint_as_float(f2tf32(sacc[mt][nt][3])));
                *(float2*)&Ps[wm + mt * 16 + gid][nt * 8 + tig * 2] = v0;
                *(float2*)&Ps[wm + mt * 16 + gid + 8][nt * 8 + tig * 2] = v1;
            }
        }
        __syncwarp();

        // O += P V (V already tf32 -> raw transposed fragment reads).
#pragma unroll
        for (int ks = 0; ks < 8; ks++) {
            const int kb = ks * 8;
            uint32_t a[2][4];
#pragma unroll
            for (int mt = 0; mt < 2; mt++) {
                const float* ap = &Ps[wm + mt * 16 + gid][kb + tig];
                a[mt][0] = __float_as_uint(ap[0]);
                a[mt][2] = __float_as_uint(ap[4]);
                const float* ap8 = &Ps[wm + mt * 16 + gid + 8][kb + tig];
                a[mt][1] = __float_as_uint(ap8[0]);
                a[mt][3] = __float_as_uint(ap8[4]);
            }
#pragma unroll
            for (int nt = 0; nt < 8; nt++) {
                uint32_t bf[2];
                bf[0] = __float_as_uint(Vs[kb + tig][nt * 8 + gid]);
                bf[1] = __float_as_uint(Vs[kb + tig + 4][nt * 8 + gid]);
                mma_tf32(oacc[0][nt], a[0], bf);
                mma_tf32(oacc[1][nt], a[1], bf);
            }
        }

        __syncthreads();
        if (kt + 2 < ntile) load_kv(slot, kt + 2);
    }

    // Epilogue: normalize, round to tf32 (feeds final GEMM), write.
#pragma unroll
    for (int mt = 0; mt < 2; mt++) {
        const float inv0 = 1.0f / lrow[mt][0], inv1 = 1.0f / lrow[mt][1];
        const int r0 = wm + mt * 16 + gid, r1 = r0 + 8;
#pragma unroll
        for (int nt = 0; nt < 8; nt++) {
            const int c = nt * 8 + tig * 2;
            float2 v0 = make_float2(f2tf32f(oacc[mt][nt][0] * inv0),
                                    f2tf32f(oacc[mt][nt][1] * inv0));
            float2 v1 = make_float2(f2tf32f(oacc[mt][nt][2] * inv1),
                                    f2tf32f(oacc[mt][nt][3] * inv1));
            *(float2*)(Ob + (size_t)r0 * EMB + c) = v0;
            *(float2*)(Ob + (size_t)r1 * EMB + c) = v1;
        }
    }
}

// ---------------------------------------------------------------------------
// Launch
// ---------------------------------------------------------------------------
extern "C" void kernel_launch(void* const* d_in, const int* in_sizes, int n_in,
                              void* d_out, int out_size)
{
    const float* query = (const float*)d_in[0];
    const float* key   = (const float*)d_in[1];
    const float* value = (const float*)d_in[2];
    const float* bq    = (const float*)d_in[4];
    const float* bk    = (const float*)d_in[6];
    const float* bv    = (const float*)d_in[8];
    const float* bo    = (const float*)d_in[10];
    float* out = (float*)d_out;

    float *pQ, *pK, *pV, *pA, *pQR, *pKR, *pVR, *pWQ, *pWK, *pWV, *pWO;
    cudaGetSymbolAddress((void**)&pQ,  g_Q);
    cudaGetSymbolAddress((void**)&pK,  g_K);
    cudaGetSymbolAddress((void**)&pV,  g_V);
    cudaGetSymbolAddress((void**)&pA,  g_A);
    cudaGetSymbolAddress((void**)&pQR, g_QR);
    cudaGetSymbolAddress((void**)&pKR, g_KR);
    cudaGetSymbolAddress((void**)&pVR, g_VR);
    cudaGetSymbolAddress((void**)&pWQ, g_WQ);
    cudaGetSymbolAddress((void**)&pWK, g_WK);
    cudaGetSymbolAddress((void**)&pWV, g_WV);
    cudaGetSymbolAddress((void**)&pWO, g_WO);

    cudaFuncSetAttribute(gemm_tf32_mma,
                         cudaFuncAttributeMaxDynamicSharedMemorySize,
                         GEMM_SMEM_BYTES);
    cudaFuncSetAttribute(flash_attn_mma,
                         cudaFuncAttributeMaxDynamicSharedMemorySize,
                         ATTN_SMEM_BYTES);

    // Prologue: tf32-round inputs + weights into scratch.
    round_tf32_all<<<dim3(512, 7), 256>>>(
        query, key, value,
        (const float*)d_in[3], (const float*)d_in[5],
        (const float*)d_in[7], (const float*)d_in[9]);

    dim3 gblk(EMB / GBN, MROWS / GBM);   // (8, 32)

    gemm_tf32_mma<<<gblk, 256, GEMM_SMEM_BYTES>>>(pQR, pWQ, bq, pQ, MROWS, EMB, EMB, 1);
    gemm_tf32_mma<<<gblk, 256, GEMM_SMEM_BYTES>>>(pKR, pWK, bk, pK, MROWS, EMB, EMB, 1);
    gemm_tf32_mma<<<gblk, 256, GEMM_SMEM_BYTES>>>(pVR, pWV, bv, pV, MROWS, EMB, EMB, 1);

    dim3 gattn(SEQ / AQ, NHEAD, BATCH);  // (16, 16, 2)
    flash_attn_mma<<<gattn, 128, ATTN_SMEM_BYTES>>>();

    gemm_tf32_mma<<<gblk, 256, GEMM_SMEM_BYTES>>>(pA, pWO, bo, out, MROWS, EMB, EMB, 0);
}

// round 8
// speedup vs baseline: 3.7955x; 1.0872x over previous
#include <cuda_runtime.h>
#include <cuda_bf16.h>
#include <math.h>
#include <stdint.h>

// Problem constants
#define BATCH 2
#define SEQ   2048
#define EMB   1024
#define NHEAD 16
#define HDIM  64
#define MROWS (BATCH*SEQ)   // 4096

// ---------------------------------------------------------------------------
// Scratch (device globals; no runtime allocation allowed)
// ---------------------------------------------------------------------------
__device__ float g_Q[MROWS * EMB];
__device__ float g_K[MROWS * EMB];
__device__ float g_VT[EMB * MROWS];   // V projection output, TRANSPOSED [emb][token]
__device__ float g_A[MROWS * EMB];
// tf32-pre-rounded copies of inputs and weights
__device__ float g_QR[MROWS * EMB];
__device__ float g_KR[MROWS * EMB];
__device__ float g_VR[MROWS * EMB];
__device__ float g_WQ[EMB * EMB];
__device__ float g_WK[EMB * EMB];
__device__ float g_WV[EMB * EMB];
__device__ float g_WO[EMB * EMB];

// ---------------------------------------------------------------------------
// Helpers
// ---------------------------------------------------------------------------
__device__ __forceinline__ uint32_t smem_u32(const void* p) {
    uint32_t a;
    asm("{ .reg .u64 t; cvta.to.shared.u64 t, %1; cvt.u32.u64 %0, t; }"
        : "=r"(a) : "l"(p));
    return a;
}
__device__ __forceinline__ uint32_t f2tf32(float x) {
    uint32_t r;
    asm("cvt.rna.tf32.f32 %0, %1;" : "=r"(r) : "f"(x));
    return r;
}
__device__ __forceinline__ float f2tf32f(float x) {
    return __uint_as_float(f2tf32(x));
}
__device__ __forceinline__ float fexp2(float x) {
    float r;
    asm("ex2.approx.ftz.f32 %0, %1;" : "=f"(r) : "f"(x));
    return r;
}
__device__ __forceinline__ void mma_tf32(float* c, const uint32_t* a, const uint32_t* b) {
    asm volatile(
        "mma.sync.aligned.m16n8k8.row.col.f32.tf32.tf32.f32 "
        "{%0,%1,%2,%3}, {%4,%5,%6,%7}, {%8,%9}, {%0,%1,%2,%3};"
        : "+f"(c[0]), "+f"(c[1]), "+f"(c[2]), "+f"(c[3])
        : "r"(a[0]), "r"(a[1]), "r"(a[2]), "r"(a[3]), "r"(b[0]), "r"(b[1]));
}

// ldmatrix x4: four 8x8 b16 tiles == tf32 fragments (1 tf32 = 2 b16).
#define LDSM_X4(r, addr) \
    asm volatile("ldmatrix.sync.aligned.m8n8.x4.shared.b16 {%0,%1,%2,%3}, [%4];" \
        : "=r"((r)[0]), "=r"((r)[1]), "=r"((r)[2]), "=r"((r)[3]) : "r"(addr))

#define CP_ASYNC16(dst_u32, src_ptr) \
    asm volatile("cp.async.cg.shared.global [%0], [%1], 16;" \
                 :: "r"(dst_u32), "l"(src_ptr))
#define CP_COMMIT() asm volatile("cp.async.commit_group;")
#define CP_WAIT(n)  asm volatile("cp.async.wait_group %0;" :: "n"(n))

// ---------------------------------------------------------------------------
// Prologue: round tensors to tf32 (rna) into scratch. blockIdx.y picks tensor.
// ---------------------------------------------------------------------------
__global__ __launch_bounds__(256) void round_tf32_all(
    const float* q, const float* k, const float* v,
    const float* wq, const float* wk, const float* wv, const float* wo)
{
    const float* src; float* dst; int n;
    switch (blockIdx.y) {
        case 0: src = q;  dst = g_QR; n = MROWS * EMB; break;
        case 1: src = k;  dst = g_KR; n = MROWS * EMB; break;
        case 2: src = v;  dst = g_VR; n = MROWS * EMB; break;
        case 3: src = wq; dst = g_WQ; n = EMB * EMB;   break;
        case 4: src = wk; dst = g_WK; n = EMB * EMB;   break;
        case 5: src = wv; dst = g_WV; n = EMB * EMB;   break;
        default: src = wo; dst = g_WO; n = EMB * EMB;  break;
    }
    int n4 = n >> 2;
    for (int i = blockIdx.x * blockDim.x + threadIdx.x; i < n4;
         i += gridDim.x * blockDim.x) {
        float4 x = ((const float4*)src)[i];
        float4 y;
        y.x = f2tf32f(x.x); y.y = f2tf32f(x.y);
        y.z = f2tf32f(x.z); y.w = f2tf32f(x.w);
        ((float4*)dst)[i] = y;
    }
}

// ---------------------------------------------------------------------------
// GEMM core: C = A[M,K] @ W[N,K]^T + bias. 128x128x32 tile, 256 thr, 3-stage
// cp.async, ldmatrix fragment loads. mode: 0 plain, 1 round-tf32,
// 2 round + transposed store (C^T, ldc = MROWS).
// ---------------------------------------------------------------------------
#define GBM 128
#define GBN 128
#define GBK 32
#define PADK 36
#define GSTG_FLTS (2 * GBM * PADK)
#define GEMM_SMEM_BYTES (3 * GSTG_FLTS * 4)         // 110592

__device__ __forceinline__ void gemm_core(
    const float* __restrict__ A, const float* __restrict__ W,
    const float* __restrict__ bias, float* __restrict__ C, int mode)
{
    extern __shared__ float smem[];
    const int M = MROWS, N = EMB, K = EMB;

    const int tid  = threadIdx.x;
    const int lane = tid & 31;
    const int warp = tid >> 5;
    const int bm = blockIdx.y * GBM;
    const int bn = blockIdx.x * GBN;

    const int wm = (warp >> 2) * 64;
    const int wn = (warp & 3) * 32;
    const int gid = lane >> 2;
    const int tig = lane & 3;

    // ldmatrix per-lane word offsets
    const int aoff = (wm + (lane & 15)) * PADK + (lane >> 4) * 4;
    const int boff = (wn + (lane & 7)) * PADK + (lane >> 3) * 4;

    float acc[4][4][4];
#pragma unroll
    for (int mt = 0; mt < 4; mt++)
#pragma unroll
        for (int nt = 0; nt < 4; nt++)
#pragma unroll
            for (int r = 0; r < 4; r++) acc[mt][nt][r] = 0.f;

    auto load_stage = [&](int s, int k0) {
        float* As = smem + s * GSTG_FLTS;
        float* Bs = As + GBM * PADK;
#pragma unroll
        for (int p = 0; p < 4; p++) {
            int idx = tid + p * 256;
            int row = idx >> 3;
            int c   = (idx & 7) * 4;
            CP_ASYNC16(smem_u32(As + row * PADK + c),
                       A + (size_t)(bm + row) * K + k0 + c);
            CP_ASYNC16(smem_u32(Bs + row * PADK + c),
                       W + (size_t)(bn + row) * K + k0 + c);
        }
        CP_COMMIT();
    };

    const int nchunk = K / GBK;
    load_stage(0, 0);
    load_stage(1, GBK);

    for (int i = 0; i < nchunk; i++) {
        CP_WAIT(1);
        __syncthreads();
        if (i + 2 < nchunk) load_stage((i + 2) % 3, (i + 2) * GBK);

        const float* As = smem + (i % 3) * GSTG_FLTS;
        const uint32_t abase = smem_u32(As);
        const uint32_t bbase = abase + GBM * PADK * 4;

#pragma unroll
        for (int ks2 = 0; ks2 < 2; ks2++) {
            uint32_t bfr[4][4];
#pragma unroll
            for (int nt = 0; nt < 4; nt++)
                LDSM_X4(bfr[nt], bbase + 4u * (boff + nt * 8 * PADK + ks2 * 16));
#pragma unroll
            for (int ksl = 0; ksl < 2; ksl++) {
                uint32_t afr[4][4];
#pragma unroll
                for (int mt = 0; mt < 4; mt++)
                    LDSM_X4(afr[mt],
                            abase + 4u * (aoff + mt * 16 * PADK + (ks2 * 2 + ksl) * 8));
#pragma unroll
                for (int mt = 0; mt < 4; mt++)
#pragma unroll
                    for (int nt = 0; nt < 4; nt++)
                        mma_tf32(acc[mt][nt], afr[mt], &bfr[nt][ksl * 2]);
            }
        }
        __syncthreads();
    }

#pragma unroll
    for (int nt = 0; nt < 4; nt++) {
        const int c0 = bn + wn + nt * 8 + tig * 2;
        const float b0 = bias[c0], b1 = bias[c0 + 1];
#pragma unroll
        for (int mt = 0; mt < 4; mt++) {
            const int r0 = bm + wm + mt * 16 + gid;
            float2 v0 = make_float2(acc[mt][nt][0] + b0, acc[mt][nt][1] + b1);
            float2 v1 = make_float2(acc[mt][nt][2] + b0, acc[mt][nt][3] + b1);
            if (mode >= 1) {
                v0.x = f2tf32f(v0.x); v0.y = f2tf32f(v0.y);
                v1.x = f2tf32f(v1.x); v1.y = f2tf32f(v1.y);
            }
            if (mode == 2) {   // transposed: C[col][row], ldc = M
                C[(size_t)c0 * M + r0]           = v0.x;
                C[(size_t)(c0 + 1) * M + r0]     = v0.y;
                C[(size_t)c0 * M + r0 + 8]       = v1.x;
                C[(size_t)(c0 + 1) * M + r0 + 8] = v1.y;
            } else {
                *(float2*)(C + (size_t)r0 * N + c0) = v0;
                *(float2*)(C + (size_t)(r0 + 8) * N + c0) = v1;
            }
        }
    }
}

// Fused Q/K/V projection: blockIdx.z selects tensor.
__global__ __launch_bounds__(256, 2) void gemm_qkv(
    const float* __restrict__ bq, const float* __restrict__ bk,
    const float* __restrict__ bv)
{
    switch (blockIdx.z) {
        case 0: gemm_core(g_QR, g_WQ, bq, g_Q, 1); break;
        case 1: gemm_core(g_KR, g_WK, bk, g_K, 1); break;
        default: gemm_core(g_VR, g_WV, bv, g_VT, 2); break;
    }
}

// Output projection.
__global__ __launch_bounds__(256, 2) void gemm_out(
    const float* __restrict__ bo, float* __restrict__ out)
{
    gemm_core(g_A, g_WO, bo, out, 0);
}

// ---------------------------------------------------------------------------
// Flash attention, mma.sync tf32, v5: ldmatrix fragments + transposed V.
// CTA: 128 q rows, 128 threads, 4 warps (32 q rows each, mt=2).
// KV slot: K rows [0,64) key-major; V^T rows [64,128) hd-major.
// ---------------------------------------------------------------------------
#define AQ   128
#define AKV  64
#define APAD 68
#define AREG_FLTS (AQ * APAD)
#define ATTN_SMEM_BYTES (3 * AREG_FLTS * 4)   // 104448

__global__ __launch_bounds__(128, 2) void flash_attn_mma()
{
    extern __shared__ float dsm[];
    float* R0 = dsm;                    // Q staging -> KV slot for odd tiles
    float* R1 = dsm + AREG_FLTS;        // KV slot for even tiles
    float* PsBase = dsm + 2 * AREG_FLTS;
    float (*Ps)[APAD] = (float(*)[APAD])PsBase;

    const int qt = blockIdx.x;
    const int h  = blockIdx.y;
    const int b  = blockIdx.z;

    const float* Qb = g_Q + ((size_t)b * SEQ + qt * AQ) * EMB + h * HDIM;
    const float* Kb = g_K + (size_t)b * SEQ * EMB + h * HDIM;
    const float* Vtb = g_VT + (size_t)(h * HDIM) * MROWS + (size_t)b * SEQ;
    float*       Ob = g_A + ((size_t)b * SEQ + qt * AQ) * EMB + h * HDIM;

    const int tid  = threadIdx.x;
    const int lane = tid & 31;
    const int warp = tid >> 5;
    const int gid  = lane >> 2;
    const int tig  = lane & 3;
    const int wm   = warp * 32;

    // ldmatrix per-lane word offsets (A-style rows, B-style rows)
    const int aoff = (wm + (lane & 15)) * APAD + (lane >> 4) * 4;
    const int boff = ((lane & 7)) * APAD + (lane >> 3) * 4;

    // K rows [0,64) at slot; V^T rows (hd-major) at slot + 64*APAD.
    auto load_kv = [&](float* base, int kt) {
        const float* Kt = Kb + (size_t)kt * AKV * EMB;
        const float* Vt = Vtb + (size_t)kt * AKV;
#pragma unroll
        for (int p = 0; p < 8; p++) {
            int idx = tid + p * 128;
            int row = idx >> 4;            // 0..63
            int c   = (idx & 15) * 4;      // 0..60
            CP_ASYNC16(smem_u32(base + row * APAD + c),
                       Kt + (size_t)row * EMB + c);
            CP_ASYNC16(smem_u32(base + (AKV + row) * APAD + c),
                       Vt + (size_t)row * MROWS + c);
        }
        CP_COMMIT();
    };

    // Prologue: Q -> R0 (async), KV0 -> R1 (async).
#pragma unroll
    for (int p = 0; p < 16; p++) {
        int idx = tid + p * 128;
        int row = idx >> 4;
        int c   = (idx & 15) * 4;
        CP_ASYNC16(smem_u32(R0 + row * APAD + c),
                   Qb + (size_t)row * EMB + c);
    }
    CP_COMMIT();
    load_kv(R1, 0);

    CP_WAIT(1);
    __syncthreads();

    // Hoist Q fragments via ldmatrix; fold scale*log2e, re-round to tf32.
    const float qscale = 0.125f * 1.4426950408889634f;
    const uint32_t r0base = smem_u32(R0);
    uint32_t qfr[2][8][4];
#pragma unroll
    for (int mt = 0; mt < 2; mt++)
#pragma unroll
        for (int ks = 0; ks < 8; ks++) {
            uint32_t t[4];
            LDSM_X4(t, r0base + 4u * (aoff + mt * 16 * APAD + ks * 8));
#pragma unroll
            for (int j = 0; j < 4; j++)
                qfr[mt][ks][j] = f2tf32(__uint_as_float(t[j]) * qscale);
        }
    __syncthreads();
    load_kv(R0, 1);

    float oacc[2][8][4];
#pragma unroll
    for (int mt = 0; mt < 2; mt++)
#pragma unroll
        for (int nt = 0; nt < 8; nt++)
#pragma unroll
            for (int r = 0; r < 4; r++) oacc[mt][nt][r] = 0.f;
    float mrow[2][2], lrow[2][2];
#pragma unroll
    for (int mt = 0; mt < 2; mt++) {
        mrow[mt][0] = -1e30f; mrow[mt][1] = -1e30f;
        lrow[mt][0] = 0.f;    lrow[mt][1] = 0.f;
    }

    const uint32_t psbase = smem_u32(PsBase);
    const int ntile = SEQ / AKV;   // 32
    for (int kt = 0; kt < ntile; kt++) {
        CP_WAIT(1);
        __syncthreads();

        float* slot = (kt & 1) ? R0 : R1;
        const uint32_t kbase = smem_u32(slot);
        const uint32_t vbase = kbase + AKV * APAD * 4;

        // S = Q K^T.
        float sacc[2][8][4];
#pragma unroll
        for (int mt = 0; mt < 2; mt++)
#pragma unroll
            for (int nt = 0; nt < 8; nt++)
#pragma unroll
                for (int r = 0; r < 4; r++) sacc[mt][nt][r] = 0.f;

#pragma unroll
        for (int ks2 = 0; ks2 < 4; ks2++) {
#pragma unroll
            for (int nt = 0; nt < 8; nt++) {
                uint32_t bf[4];
                LDSM_X4(bf, kbase + 4u * (boff + nt * 8 * APAD + ks2 * 16));
                mma_tf32(sacc[0][nt], qfr[0][ks2 * 2], bf);
                mma_tf32(sacc[1][nt], qfr[1][ks2 * 2], bf);
                mma_tf32(sacc[0][nt], qfr[0][ks2 * 2 + 1], bf + 2);
                mma_tf32(sacc[1][nt], qfr[1][ks2 * 2 + 1], bf + 2);
            }
        }

        // Online softmax (exp2 domain).
#pragma unroll
        for (int mt = 0; mt < 2; mt++) {
            float mx0 = -1e30f, mx1 = -1e30f;
#pragma unroll
            for (int nt = 0; nt < 8; nt++) {
                mx0 = fmaxf(mx0, fmaxf(sacc[mt][nt][0], sacc[mt][nt][1]));
                mx1 = fmaxf(mx1, fmaxf(sacc[mt][nt][2], sacc[mt][nt][3]));
            }
            mx0 = fmaxf(mx0, __shfl_xor_sync(0xffffffffu, mx0, 1));
            mx0 = fmaxf(mx0, __shfl_xor_sync(0xffffffffu, mx0, 2));
            mx1 = fmaxf(mx1, __shfl_xor_sync(0xffffffffu, mx1, 1));
            mx1 = fmaxf(mx1, __shfl_xor_sync(0xffffffffu, mx1, 2));

            float mn0 = fmaxf(mrow[mt][0], mx0), mn1 = fmaxf(mrow[mt][1], mx1);
            float corr0 = fexp2(mrow[mt][0] - mn0), corr1 = fexp2(mrow[mt][1] - mn1);
            float s0 = 0.f, s1 = 0.f;
#pragma unroll
            for (int nt = 0; nt < 8; nt++) {
                sacc[mt][nt][0] = fexp2(sacc[mt][nt][0] - mn0);
                sacc[mt][nt][1] = fexp2(sacc[mt][nt][1] - mn0);
                sacc[mt][nt][2] = fexp2(sacc[mt][nt][2] - mn1);
                sacc[mt][nt][3] = fexp2(sacc[mt][nt][3] - mn1);
                s0 += sacc[mt][nt][0] + sacc[mt][nt][1];
                s1 += sacc[mt][nt][2] + sacc[mt][nt][3];
            }
            s0 += __shfl_xor_sync(0xffffffffu, s0, 1);
            s0 += __shfl_xor_sync(0xffffffffu, s0, 2);
            s1 += __shfl_xor_sync(0xffffffffu, s1, 1);
            s1 += __shfl_xor_sync(0xffffffffu, s1, 2);
            lrow[mt][0] = lrow[mt][0] * corr0 + s0;  mrow[mt][0] = mn0;
            lrow[mt][1] = lrow[mt][1] * corr1 + s1;  mrow[mt][1] = mn1;
#pragma unroll
            for (int nt = 0; nt < 8; nt++) {
                oacc[mt][nt][0] *= corr0; oacc[mt][nt][1] *= corr0;
                oacc[mt][nt][2] *= corr1; oacc[mt][nt][3] *= corr1;
            }

            // Stage P (tf32-rounded) into this warp's private rows of Ps.
#pragma unroll
            for (int nt = 0; nt < 8; nt++) {
                float2 v0 = make_float2(
                    __uint_as_float(f2tf32(sacc[mt][nt][0])),
                    __uint_as_float(f2tf32(sacc[mt][nt][1])));
                float2 v1 = make_float2(
                    __uint_as_float(f2tf32(sacc[mt][nt][2])),
                    __uint_as_float(f2tf32(sacc[mt][nt][3])));
                *(float2*)&Ps[wm + mt * 16 + gid][nt * 8 + tig * 2] = v0;
                *(float2*)&Ps[wm + mt * 16 + gid + 8][nt * 8 + tig * 2] = v1;
            }
        }
        __syncwarp();

        // O += P V : A = Ps via ldmatrix, B = V^T (hd-major) via ldmatrix.
#pragma unroll
        for (int ks2 = 0; ks2 < 4; ks2++) {
            uint32_t pa[2][2][4];
#pragma unroll
            for (int mt = 0; mt < 2; mt++)
#pragma unroll
                for (int ksl = 0; ksl < 2; ksl++)
                    LDSM_X4(pa[mt][ksl],
                            psbase + 4u * (aoff + mt * 16 * APAD + (ks2 * 2 + ksl) * 8));
#pragma unroll
            for (int nt = 0; nt < 8; nt++) {
                uint32_t vf[4];
                LDSM_X4(vf, vbase + 4u * (boff + nt * 8 * APAD + ks2 * 16));
                mma_tf32(oacc[0][nt], pa[0][0], vf);
                mma_tf32(oacc[1][nt], pa[1][0], vf);
                mma_tf32(oacc[0][nt], pa[0][1], vf + 2);
                mma_tf32(oacc[1][nt], pa[1][1], vf + 2);
            }
        }

        __syncthreads();
        if (kt + 2 < ntile) load_kv(slot, kt + 2);
    }

    // Epilogue: normalize, round to tf32 (feeds final GEMM), write.
#pragma unroll
    for (int mt = 0; mt < 2; mt++) {
        const float inv0 = 1.0f / lrow[mt][0], inv1 = 1.0f / lrow[mt][1];
        const int r0 = wm + mt * 16 + gid, r1 = r0 + 8;
#pragma unroll
        for (int nt = 0; nt < 8; nt++) {
            const int c = nt * 8 + tig * 2;
            float2 v0 = make_float2(f2tf32f(oacc[mt][nt][0] * inv0),
                                    f2tf32f(oacc[mt][nt][1] * inv0));
            float2 v1 = make_float2(f2tf32f(oacc[mt][nt][2] * inv1),
                                    f2tf32f(oacc[mt][nt][3] * inv1));
            *(float2*)(Ob + (size_t)r0 * EMB + c) = v0;
            *(float2*)(Ob + (size_t)r1 * EMB + c) = v1;
        }
    }
}

// ---------------------------------------------------------------------------
// Launch
// ---------------------------------------------------------------------------
extern "C" void kernel_launch(void* const* d_in, const int* in_sizes, int n_in,
                              void* d_out, int out_size)
{
    const float* query = (const float*)d_in[0];
    const float* key   = (const float*)d_in[1];
    const float* value = (const float*)d_in[2];
    const float* bq    = (const float*)d_in[4];
    const float* bk    = (const float*)d_in[6];
    const float* bv    = (const float*)d_in[8];
    const float* bo    = (const float*)d_in[10];
    float* out = (float*)d_out;

    cudaFuncSetAttribute(gemm_qkv,
                         cudaFuncAttributeMaxDynamicSharedMemorySize,
                         GEMM_SMEM_BYTES);
    cudaFuncSetAttribute(gemm_out,
                         cudaFuncAttributeMaxDynamicSharedMemorySize,
                         GEMM_SMEM_BYTES);
    cudaFuncSetAttribute(flash_attn_mma,
                         cudaFuncAttributeMaxDynamicSharedMemorySize,
                         ATTN_SMEM_BYTES);

    // Prologue: tf32-round inputs + weights into scratch.
    round_tf32_all<<<dim3(512, 7), 256>>>(
        query, key, value,
        (const float*)d_in[3], (const float*)d_in[5],
        (const float*)d_in[7], (const float*)d_in[9]);

    dim3 gqkv(EMB / GBN, MROWS / GBM, 3);   // (8, 32, 3)
    gemm_qkv<<<gqkv, 256, GEMM_SMEM_BYTES>>>(bq, bk, bv);

    dim3 gattn(SEQ / AQ, NHEAD, BATCH);  // (16, 16, 2)
    flash_attn_mma<<<gattn, 128, ATTN_SMEM_BYTES>>>();

    dim3 gout(EMB / GBN, MROWS / GBM);   // (8, 32)
    gemm_out<<<gout, 256, GEMM_SMEM_BYTES>>>(bo, out);
}

// round 10
// speedup vs baseline: 3.9545x; 1.0419x over previous
#include <cuda_runtime.h>
#include <cuda_bf16.h>
#include <math.h>
#include <stdint.h>

// Problem constants
#define BATCH 2
#define SEQ   2048
#define EMB   1024
#define NHEAD 16
#define HDIM  64
#define MROWS (BATCH*SEQ)   // 4096

// ---------------------------------------------------------------------------
// Scratch (device globals; no runtime allocation allowed)
// ---------------------------------------------------------------------------
__device__ float g_Q[MROWS * EMB];
__device__ float g_K[MROWS * EMB];
__device__ float g_VT[EMB * MROWS];   // V projection output, TRANSPOSED [emb][token]
__device__ float g_A[MROWS * EMB];
// tf32-pre-rounded copies of inputs and weights
__device__ float g_QR[MROWS * EMB];
__device__ float g_KR[MROWS * EMB];
__device__ float g_VR[MROWS * EMB];
__device__ float g_WQ[EMB * EMB];
__device__ float g_WK[EMB * EMB];
__device__ float g_WV[EMB * EMB];
__device__ float g_WO[EMB * EMB];

// ---------------------------------------------------------------------------
// Helpers
// ---------------------------------------------------------------------------
__device__ __forceinline__ uint32_t smem_u32(const void* p) {
    uint32_t a;
    asm("{ .reg .u64 t; cvta.to.shared.u64 t, %1; cvt.u32.u64 %0, t; }"
        : "=r"(a) : "l"(p));
    return a;
}
__device__ __forceinline__ uint32_t f2tf32(float x) {
    uint32_t r;
    asm("cvt.rna.tf32.f32 %0, %1;" : "=r"(r) : "f"(x));
    return r;
}
__device__ __forceinline__ float f2tf32f(float x) {
    return __uint_as_float(f2tf32(x));
}
__device__ __forceinline__ float fexp2(float x) {
    float r;
    asm("ex2.approx.ftz.f32 %0, %1;" : "=f"(r) : "f"(x));
    return r;
}
__device__ __forceinline__ void mma_tf32(float* c, const uint32_t* a, const uint32_t* b) {
    asm volatile(
        "mma.sync.aligned.m16n8k8.row.col.f32.tf32.tf32.f32 "
        "{%0,%1,%2,%3}, {%4,%5,%6,%7}, {%8,%9}, {%0,%1,%2,%3};"
        : "+f"(c[0]), "+f"(c[1]), "+f"(c[2]), "+f"(c[3])
        : "r"(a[0]), "r"(a[1]), "r"(a[2]), "r"(a[3]), "r"(b[0]), "r"(b[1]));
}

// ldmatrix x4: four 8x8 b16 tiles == tf32 fragments (1 tf32 = 2 b16).
#define LDSM_X4(r, addr) \
    asm volatile("ldmatrix.sync.aligned.m8n8.x4.shared.b16 {%0,%1,%2,%3}, [%4];" \
        : "=r"((r)[0]), "=r"((r)[1]), "=r"((r)[2]), "=r"((r)[3]) : "r"(addr))

#define CP_ASYNC16(dst_u32, src_ptr) \
    asm volatile("cp.async.cg.shared.global [%0], [%1], 16;" \
                 :: "r"(dst_u32), "l"(src_ptr))
#define CP_COMMIT() asm volatile("cp.async.commit_group;")
#define CP_WAIT(n)  asm volatile("cp.async.wait_group %0;" :: "n"(n))

// ---------------------------------------------------------------------------
// Prologue: round tensors to tf32 (rna) into scratch. blockIdx.y picks tensor.
// ---------------------------------------------------------------------------
__global__ __launch_bounds__(256) void round_tf32_all(
    const float* q, const float* k, const float* v,
    const float* wq, const float* wk, const float* wv, const float* wo)
{
    const float* src; float* dst; int n;
    switch (blockIdx.y) {
        case 0: src = q;  dst = g_QR; n = MROWS * EMB; break;
        case 1: src = k;  dst = g_KR; n = MROWS * EMB; break;
        case 2: src = v;  dst = g_VR; n = MROWS * EMB; break;
        case 3: src = wq; dst = g_WQ; n = EMB * EMB;   break;
        case 4: src = wk; dst = g_WK; n = EMB * EMB;   break;
        case 5: src = wv; dst = g_WV; n = EMB * EMB;   break;
        default: src = wo; dst = g_WO; n = EMB * EMB;  break;
    }
    int n4 = n >> 2;
    for (int i = blockIdx.x * blockDim.x + threadIdx.x; i < n4;
         i += gridDim.x * blockDim.x) {
        float4 x = ((const float4*)src)[i];
        float4 y;
        y.x = f2tf32f(x.x); y.y = f2tf32f(x.y);
        y.z = f2tf32f(x.z); y.w = f2tf32f(x.w);
        ((float4*)dst)[i] = y;
    }
}

// ---------------------------------------------------------------------------
// GEMM core: C = A[M,K] @ W[N,K]^T + bias. 128x128x32 tile, 256 thr, 3-stage
// cp.async, ldmatrix fragment loads. Single barrier per chunk (ring-safety
// carried by the top CP_WAIT+barrier); next-stage loads issued mid-chunk.
// mode: 0 plain, 1 round-tf32, 2 round + transposed store (C^T, ldc=MROWS).
// ---------------------------------------------------------------------------
#define GBM 128
#define GBN 128
#define GBK 32
#define PADK 36
#define GSTG_FLTS (2 * GBM * PADK)
#define GEMM_SMEM_BYTES (3 * GSTG_FLTS * 4)         // 110592

__device__ __forceinline__ void gemm_core(
    const float* __restrict__ A, const float* __restrict__ W,
    const float* __restrict__ bias, float* __restrict__ C, int mode)
{
    extern __shared__ float smem[];
    const int M = MROWS, N = EMB, K = EMB;

    const int tid  = threadIdx.x;
    const int lane = tid & 31;
    const int warp = tid >> 5;
    const int bm = blockIdx.y * GBM;
    const int bn = blockIdx.x * GBN;

    const int wm = (warp >> 2) * 64;
    const int wn = (warp & 3) * 32;
    const int gid = lane >> 2;
    const int tig = lane & 3;

    // ldmatrix per-lane word offsets
    const int aoff = (wm + (lane & 15)) * PADK + (lane >> 4) * 4;
    const int boff = (wn + (lane & 7)) * PADK + (lane >> 3) * 4;

    float acc[4][4][4];
#pragma unroll
    for (int mt = 0; mt < 4; mt++)
#pragma unroll
        for (int nt = 0; nt < 4; nt++)
#pragma unroll
            for (int r = 0; r < 4; r++) acc[mt][nt][r] = 0.f;

    auto load_stage = [&](int s, int k0) {
        float* As = smem + s * GSTG_FLTS;
        float* Bs = As + GBM * PADK;
#pragma unroll
        for (int p = 0; p < 4; p++) {
            int idx = tid + p * 256;
            int row = idx >> 3;
            int c   = (idx & 7) * 4;
            CP_ASYNC16(smem_u32(As + row * PADK + c),
                       A + (size_t)(bm + row) * K + k0 + c);
            CP_ASYNC16(smem_u32(Bs + row * PADK + c),
                       W + (size_t)(bn + row) * K + k0 + c);
        }
        CP_COMMIT();
    };

    // one k16 half-chunk of compute: 4 B-ldsm, 2x(4 A-ldsm + 16 mma)
    auto compute_half = [&](uint32_t abase, uint32_t bbase, int ks2) {
        uint32_t bfr[4][4];
#pragma unroll
        for (int nt = 0; nt < 4; nt++)
            LDSM_X4(bfr[nt], bbase + 4u * (boff + nt * 8 * PADK + ks2 * 16));
#pragma unroll
        for (int ksl = 0; ksl < 2; ksl++) {
            uint32_t afr[4][4];
#pragma unroll
            for (int mt = 0; mt < 4; mt++)
                LDSM_X4(afr[mt],
                        abase + 4u * (aoff + mt * 16 * PADK + (ks2 * 2 + ksl) * 8));
#pragma unroll
            for (int mt = 0; mt < 4; mt++)
#pragma unroll
                for (int nt = 0; nt < 4; nt++)
                    mma_tf32(acc[mt][nt], afr[mt], &bfr[nt][ksl * 2]);
        }
    };

    const int nchunk = K / GBK;
    load_stage(0, 0);
    load_stage(1, GBK);

    for (int i = 0; i < nchunk; i++) {
        CP_WAIT(1);
        __syncthreads();
        // Ring safety: stage (i+2)%3 == stage (i-1)%3 was fully read before
        // every warp passed the barrier above. No trailing barrier needed.
        const uint32_t abase = smem_u32(smem + (i % 3) * GSTG_FLTS);
        const uint32_t bbase = abase + GBM * PADK * 4;

        compute_half(abase, bbase, 0);          // fragments get LSU first
        if (i + 2 < nchunk) load_stage((i + 2) % 3, (i + 2) * GBK);
        compute_half(abase, bbase, 1);
    }

#pragma unroll
    for (int nt = 0; nt < 4; nt++) {
        const int c0 = bn + wn + nt * 8 + tig * 2;
        const float b0 = bias[c0], b1 = bias[c0 + 1];
#pragma unroll
        for (int mt = 0; mt < 4; mt++) {
            const int r0 = bm + wm + mt * 16 + gid;
            float2 v0 = make_float2(acc[mt][nt][0] + b0, acc[mt][nt][1] + b1);
            float2 v1 = make_float2(acc[mt][nt][2] + b0, acc[mt][nt][3] + b1);
            if (mode >= 1) {
                v0.x = f2tf32f(v0.x); v0.y = f2tf32f(v0.y);
                v1.x = f2tf32f(v1.x); v1.y = f2tf32f(v1.y);
            }
            if (mode == 2) {   // transposed: C[col][row], ldc = M
                C[(size_t)c0 * M + r0]           = v0.x;
                C[(size_t)(c0 + 1) * M + r0]     = v0.y;
                C[(size_t)c0 * M + r0 + 8]       = v1.x;
                C[(size_t)(c0 + 1) * M + r0 + 8] = v1.y;
            } else {
                *(float2*)(C + (size_t)r0 * N + c0) = v0;
                *(float2*)(C + (size_t)(r0 + 8) * N + c0) = v1;
            }
        }
    }
}

// Fused Q/K/V projection: blockIdx.z selects tensor.
__global__ __launch_bounds__(256, 2) void gemm_qkv(
    const float* __restrict__ bq, const float* __restrict__ bk,
    const float* __restrict__ bv)
{
    switch (blockIdx.z) {
        case 0: gemm_core(g_QR, g_WQ, bq, g_Q, 1); break;
        case 1: gemm_core(g_KR, g_WK, bk, g_K, 1); break;
        default: gemm_core(g_VR, g_WV, bv, g_VT, 2); break;
    }
}

// Output projection.
__global__ __launch_bounds__(256, 2) void gemm_out(
    const float* __restrict__ bo, float* __restrict__ out)
{
    gemm_core(g_A, g_WO, bo, out, 0);
}

// ---------------------------------------------------------------------------
// Flash attention, mma.sync tf32: ldmatrix fragments + transposed V.
// CTA: 128 q rows, 128 threads, 4 warps (32 q rows each, mt=2).
// KV slot: K rows [0,64) key-major; V^T rows [64,128) hd-major.
// ---------------------------------------------------------------------------
#define AQ   128
#define AKV  64
#define APAD 68
#define AREG_FLTS (AQ * APAD)
#define ATTN_SMEM_BYTES (3 * AREG_FLTS * 4)   // 104448

__global__ __launch_bounds__(128, 2) void flash_attn_mma()
{
    extern __shared__ float dsm[];
    float* R0 = dsm;                    // Q staging -> KV slot for odd tiles
    float* R1 = dsm + AREG_FLTS;        // KV slot for even tiles
    float* PsBase = dsm + 2 * AREG_FLTS;
    float (*Ps)[APAD] = (float(*)[APAD])PsBase;

    const int qt = blockIdx.x;
    const int h  = blockIdx.y;
    const int b  = blockIdx.z;

    const float* Qb = g_Q + ((size_t)b * SEQ + qt * AQ) * EMB + h * HDIM;
    const float* Kb = g_K + (size_t)b * SEQ * EMB + h * HDIM;
    const float* Vtb = g_VT + (size_t)(h * HDIM) * MROWS + (size_t)b * SEQ;
    float*       Ob = g_A + ((size_t)b * SEQ + qt * AQ) * EMB + h * HDIM;

    const int tid  = threadIdx.x;
    const int lane = tid & 31;
    const int warp = tid >> 5;
    const int gid  = lane >> 2;
    const int tig  = lane & 3;
    const int wm   = warp * 32;

    // ldmatrix per-lane word offsets (A-style rows, B-style rows)
    const int aoff = (wm + (lane & 15)) * APAD + (lane >> 4) * 4;
    const int boff = ((lane & 7)) * APAD + (lane >> 3) * 4;

    // K rows [0,64) at slot; V^T rows (hd-major) at slot + 64*APAD.
    auto load_kv = [&](float* base, int kt) {
        const float* Kt = Kb + (size_t)kt * AKV * EMB;
        const float* Vt = Vtb + (size_t)kt * AKV;
#pragma unroll
        for (int p = 0; p < 8; p++) {
            int idx = tid + p * 128;
            int row = idx >> 4;            // 0..63
            int c   = (idx & 15) * 4;      // 0..60
            CP_ASYNC16(smem_u32(base + row * APAD + c),
                       Kt + (size_t)row * EMB + c);
            CP_ASYNC16(smem_u32(base + (AKV + row) * APAD + c),
                       Vt + (size_t)row * MROWS + c);
        }
        CP_COMMIT();
    };

    // Prologue: Q -> R0 (async), KV0 -> R1 (async).
#pragma unroll
    for (int p = 0; p < 16; p++) {
        int idx = tid + p * 128;
        int row = idx >> 4;
        int c   = (idx & 15) * 4;
        CP_ASYNC16(smem_u32(R0 + row * APAD + c),
                   Qb + (size_t)row * EMB + c);
    }
    CP_COMMIT();
    load_kv(R1, 0);

    CP_WAIT(1);
    __syncthreads();

    // Hoist Q fragments via ldmatrix; fold scale*log2e, re-round to tf32.
    const float qscale = 0.125f * 1.4426950408889634f;
    const uint32_t r0base = smem_u32(R0);
    uint32_t qfr[2][8][4];
#pragma unroll
    for (int mt = 0; mt < 2; mt++)
#pragma unroll
        for (int ks = 0; ks < 8; ks++) {
            uint32_t t[4];
            LDSM_X4(t, r0base + 4u * (aoff + mt * 16 * APAD + ks * 8));
#pragma unroll
            for (int j = 0; j < 4; j++)
                qfr[mt][ks][j] = f2tf32(__uint_as_float(t[j]) * qscale);
        }
    __syncthreads();
    load_kv(R0, 1);

    float oacc[2][8][4];
#pragma unroll
    for (int mt = 0; mt < 2; mt++)
#pragma unroll
        for (int nt = 0; nt < 8; nt++)
#pragma unroll
            for (int r = 0; r < 4; r++) oacc[mt][nt][r] = 0.f;
    float mrow[2][2], lrow[2][2];
#pragma unroll
    for (int mt = 0; mt < 2; mt++) {
        mrow[mt][0] = -1e30f; mrow[mt][1] = -1e30f;
        lrow[mt][0] = 0.f;    lrow[mt][1] = 0.f;
    }

    const uint32_t psbase = smem_u32(PsBase);
    const int ntile = SEQ / AKV;   // 32
    for (int kt = 0; kt < ntile; kt++) {
        CP_WAIT(1);
        __syncthreads();

        float* slot = (kt & 1) ? R0 : R1;
        const uint32_t kbase = smem_u32(slot);
        const uint32_t vbase = kbase + AKV * APAD * 4;

        // S = Q K^T.
        float sacc[2][8][4];
#pragma unroll
        for (int mt = 0; mt < 2; mt++)
#pragma unroll
            for (int nt = 0; nt < 8; nt++)
#pragma unroll
                for (int r = 0; r < 4; r++) sacc[mt][nt][r] = 0.f;

#pragma unroll
        for (int ks2 = 0; ks2 < 4; ks2++) {
#pragma unroll
            for (int nt = 0; nt < 8; nt++) {
                uint32_t bf[4];
                LDSM_X4(bf, kbase + 4u * (boff + nt * 8 * APAD + ks2 * 16));
                mma_tf32(sacc[0][nt], qfr[0][ks2 * 2], bf);
                mma_tf32(sacc[1][nt], qfr[1][ks2 * 2], bf);
                mma_tf32(sacc[0][nt], qfr[0][ks2 * 2 + 1], bf + 2);
                mma_tf32(sacc[1][nt], qfr[1][ks2 * 2 + 1], bf + 2);
            }
        }

        // Online softmax (exp2 domain).
#pragma unroll
        for (int mt = 0; mt < 2; mt++) {
            float mx0 = -1e30f, mx1 = -1e30f;
#pragma unroll
            for (int nt = 0; nt < 8; nt++) {
                mx0 = fmaxf(mx0, fmaxf(sacc[mt][nt][0], sacc[mt][nt][1]));
                mx1 = fmaxf(mx1, fmaxf(sacc[mt][nt][2], sacc[mt][nt][3]));
            }
            mx0 = fmaxf(mx0, __shfl_xor_sync(0xffffffffu, mx0, 1));
            mx0 = fmaxf(mx0, __shfl_xor_sync(0xffffffffu, mx0, 2));
            mx1 = fmaxf(mx1, __shfl_xor_sync(0xffffffffu, mx1, 1));
            mx1 = fmaxf(mx1, __shfl_xor_sync(0xffffffffu, mx1, 2));

            float mn0 = fmaxf(mrow[mt][0], mx0), mn1 = fmaxf(mrow[mt][1], mx1);
            float corr0 = fexp2(mrow[mt][0] - mn0), corr1 = fexp2(mrow[mt][1] - mn1);
            float s0 = 0.f, s1 = 0.f;
#pragma unroll
            for (int nt = 0; nt < 8; nt++) {
                sacc[mt][nt][0] = fexp2(sacc[mt][nt][0] - mn0);
                sacc[mt][nt][1] = fexp2(sacc[mt][nt][1] - mn0);
                sacc[mt][nt][2] = fexp2(sacc[mt][nt][2] - mn1);
                sacc[mt][nt][3] = fexp2(sacc[mt][nt][3] - mn1);
                s0 += sacc[mt][nt][0] + sacc[mt][nt][1];
                s1 += sacc[mt][nt][2] + sacc[mt][nt][3];
            }
            s0 += __shfl_xor_sync(0xffffffffu, s0, 1);
            s0 += __shfl_xor_sync(0xffffffffu, s0, 2);
            s1 += __shfl_xor_sync(0xffffffffu, s1, 1);
            s1 += __shfl_xor_sync(0xffffffffu, s1, 2);
            lrow[mt][0] = lrow[mt][0] * corr0 + s0;  mrow[mt][0] = mn0;
            lrow[mt][1] = lrow[mt][1] * corr1 + s1;  mrow[mt][1] = mn1;
#pragma unroll
            for (int nt = 0; nt < 8; nt++) {
                oacc[mt][nt][0] *= corr0; oacc[mt][nt][1] *= corr0;
                oacc[mt][nt][2] *= corr1; oacc[mt][nt][3] *= corr1;
            }

            // Stage P (tf32-rounded) into this warp's private rows of Ps.
#pragma unroll
            for (int nt = 0; nt < 8; nt++) {
                float2 v0 = make_float2(
                    __uint_as_float(f2tf32(sacc[mt][nt][0])),
                    __uint_as_float(f2tf32(sacc[mt][nt][1])));
                float2 v1 = make_float2(
                    __uint_as_float(f2tf32(sacc[mt][nt][2])),
                    __uint_as_float(f2tf32(sacc[mt][nt][3])));
                *(float2*)&Ps[wm + mt * 16 + gid][nt * 8 + tig * 2] = v0;
                *(float2*)&Ps[wm + mt * 16 + gid + 8][nt * 8 + tig * 2] = v1;
            }
        }
        __syncwarp();

        // O += P V : A = Ps via ldmatrix, B = V^T (hd-major) via ldmatrix.
#pragma unroll
        for (int ks2 = 0; ks2 < 4; ks2++) {
            uint32_t pa[2][2][4];
#pragma unroll
            for (int mt = 0; mt < 2; mt++)
#pragma unroll
                for (int ksl = 0; ksl < 2; ksl++)
                    LDSM_X4(pa[mt][ksl],
                            psbase + 4u * (aoff + mt * 16 * APAD + (ks2 * 2 + ksl) * 8));
#pragma unroll
            for (int nt = 0; nt < 8; nt++) {
                uint32_t vf[4];
                LDSM_X4(vf, vbase + 4u * (boff + nt * 8 * APAD + ks2 * 16));
                mma_tf32(oacc[0][nt], pa[0][0], vf);
                mma_tf32(oacc[1][nt], pa[1][0], vf);
                mma_tf32(oacc[0][nt], pa[0][1], vf + 2);
                mma_tf32(oacc[1][nt], pa[1][1], vf + 2);
            }
        }

        __syncthreads();
        if (kt + 2 < ntile) load_kv(slot, kt + 2);
    }

    // Epilogue: normalize, round to tf32 (feeds final GEMM), write.
#pragma unroll
    for (int mt = 0; mt < 2; mt++) {
        const float inv0 = 1.0f / lrow[mt][0], inv1 = 1.0f / lrow[mt][1];
        const int r0 = wm + mt * 16 + gid, r1 = r0 + 8;
#pragma unroll
        for (int nt = 0; nt < 8; nt++) {
            const int c = nt * 8 + tig * 2;
            float2 v0 = make_float2(f2tf32f(oacc[mt][nt][0] * inv0),
                                    f2tf32f(oacc[mt][nt][1] * inv0));
            float2 v1 = make_float2(f2tf32f(oacc[mt][nt][2] * inv1),
                                    f2tf32f(oacc[mt][nt][3] * inv1));
            *(float2*)(Ob + (size_t)r0 * EMB + c) = v0;
            *(float2*)(Ob + (size_t)r1 * EMB + c) = v1;
        }
    }
}

// ---------------------------------------------------------------------------
// Launch
// ---------------------------------------------------------------------------
extern "C" void kernel_launch(void* const* d_in, const int* in_sizes, int n_in,
                              void* d_out, int out_size)
{
    const float* query = (const float*)d_in[0];
    const float* key   = (const float*)d_in[1];
    const float* value = (const float*)d_in[2];
    const float* bq    = (const float*)d_in[4];
    const float* bk    = (const float*)d_in[6];
    const float* bv    = (const float*)d_in[8];
    const float* bo    = (const float*)d_in[10];
    float* out = (float*)d_out;

    cudaFuncSetAttribute(gemm_qkv,
                         cudaFuncAttributeMaxDynamicSharedMemorySize,
                         GEMM_SMEM_BYTES);
    cudaFuncSetAttribute(gemm_out,
                         cudaFuncAttributeMaxDynamicSharedMemorySize,
                         GEMM_SMEM_BYTES);
    cudaFuncSetAttribute(flash_attn_mma,
                         cudaFuncAttributeMaxDynamicSharedMemorySize,
                         ATTN_SMEM_BYTES);

    // Prologue: tf32-round inputs + weights into scratch.
    round_tf32_all<<<dim3(512, 7), 256>>>(
        query, key, value,
        (const float*)d_in[3], (const float*)d_in[5],
        (const float*)d_in[7], (const float*)d_in[9]);

    dim3 gqkv(EMB / GBN, MROWS / GBM, 3);   // (8, 32, 3)
    gemm_qkv<<<gqkv, 256, GEMM_SMEM_BYTES>>>(bq, bk, bv);

    dim3 gattn(SEQ / AQ, NHEAD, BATCH);  // (16, 16, 2)
    flash_attn_mma<<<gattn, 128, ATTN_SMEM_BYTES>>>();

    dim3 gout(EMB / GBN, MROWS / GBM);   // (8, 32)
    gemm_out<<<gout, 256, GEMM_SMEM_BYTES>>>(bo, out);
}

// round 11
// speedup vs baseline: 7.3152x; 1.8498x over previous
#include <cuda_runtime.h>
#include <cuda_fp16.h>
#include <math.h>
#include <stdint.h>

// Problem constants
#define BATCH 2
#define SEQ   2048
#define EMB   1024
#define NHEAD 16
#define HDIM  64
#define MROWS (BATCH*SEQ)   // 4096

// ---------------------------------------------------------------------------
// Scratch (device globals; no runtime allocation allowed) — all fp16
// ---------------------------------------------------------------------------
__device__ __half g_Q[MROWS * EMB];
__device__ __half g_K[MROWS * EMB];
__device__ __half g_VT[EMB * MROWS];   // V projection output, TRANSPOSED [emb][token]
__device__ __half g_A[MROWS * EMB];    // attention output O
// fp16-pre-rounded copies of inputs and weights
__device__ __half g_QR[MROWS * EMB];
__device__ __half g_KR[MROWS * EMB];
__device__ __half g_VR[MROWS * EMB];
__device__ __half g_WQ[EMB * EMB];
__device__ __half g_WK[EMB * EMB];
__device__ __half g_WV[EMB * EMB];
__device__ __half g_WO[EMB * EMB];

// ---------------------------------------------------------------------------
// Helpers
// ---------------------------------------------------------------------------
__device__ __forceinline__ uint32_t smem_u32(const void* p) {
    uint32_t a;
    asm("{ .reg .u64 t; cvta.to.shared.u64 t, %1; cvt.u32.u64 %0, t; }"
        : "=r"(a) : "l"(p));
    return a;
}
__device__ __forceinline__ float fexp2(float x) {
    float r;
    asm("ex2.approx.ftz.f32 %0, %1;" : "=f"(r) : "f"(x));
    return r;
}
__device__ __forceinline__ void mma_f16(float* c, const uint32_t* a, const uint32_t* b) {
    asm volatile(
        "mma.sync.aligned.m16n8k16.row.col.f32.f16.f16.f32 "
        "{%0,%1,%2,%3}, {%4,%5,%6,%7}, {%8,%9}, {%0,%1,%2,%3};"
        : "+f"(c[0]), "+f"(c[1]), "+f"(c[2]), "+f"(c[3])
        : "r"(a[0]), "r"(a[1]), "r"(a[2]), "r"(a[3]), "r"(b[0]), "r"(b[1]));
}

// ldmatrix x4: four 8x8 b16 tiles (native fp16)
#define LDSM_X4(r, addr) \
    asm volatile("ldmatrix.sync.aligned.m8n8.x4.shared.b16 {%0,%1,%2,%3}, [%4];" \
        : "=r"((r)[0]), "=r"((r)[1]), "=r"((r)[2]), "=r"((r)[3]) : "r"(addr))

#define CP_ASYNC16(dst_u32, src_ptr) \
    asm volatile("cp.async.cg.shared.global [%0], [%1], 16;" \
                 :: "r"(dst_u32), "l"(src_ptr))
#define CP_COMMIT() asm volatile("cp.async.commit_group;")
#define CP_WAIT(n)  asm volatile("cp.async.wait_group %0;" :: "n"(n))

// ---------------------------------------------------------------------------
// Prologue: round tensors to fp16 (rn) into scratch. blockIdx.y picks tensor.
// ---------------------------------------------------------------------------
__global__ __launch_bounds__(256) void round_f16_all(
    const float* q, const float* k, const float* v,
    const float* wq, const float* wk, const float* wv, const float* wo)
{
    const float* src; __half* dst; int n;
    switch (blockIdx.y) {
        case 0: src = q;  dst = g_QR; n = MROWS * EMB; break;
        case 1: src = k;  dst = g_KR; n = MROWS * EMB; break;
        case 2: src = v;  dst = g_VR; n = MROWS * EMB; break;
        case 3: src = wq; dst = g_WQ; n = EMB * EMB;   break;
        case 4: src = wk; dst = g_WK; n = EMB * EMB;   break;
        case 5: src = wv; dst = g_WV; n = EMB * EMB;   break;
        default: src = wo; dst = g_WO; n = EMB * EMB;  break;
    }
    int n4 = n >> 2;
    for (int i = blockIdx.x * blockDim.x + threadIdx.x; i < n4;
         i += gridDim.x * blockDim.x) {
        float4 x = ((const float4*)src)[i];
        __half2* d = (__half2*)(dst + (size_t)i * 4);
        d[0] = __floats2half2_rn(x.x, x.y);
        d[1] = __floats2half2_rn(x.z, x.w);
    }
}

// ---------------------------------------------------------------------------
// GEMM core (fp16 operands, fp32 accum): C = A[M,K] @ W[N,K]^T + bias.
// 128x128x64 tile, 256 thr, 3-stage cp.async ring, single barrier per chunk,
// ldmatrix b16 fragments. mode: 0 fp32 C, 1 fp16 C, 2 fp16 C transposed.
// ---------------------------------------------------------------------------
#define GBM 128
#define GBN 128
#define GBK 64
#define PADH 72                                   // halfs per smem row
#define GSTG_HALFS (2 * GBM * PADH)               // A+B per stage = 18432
#define GEMM_SMEM_BYTES (3 * GSTG_HALFS * 2)      // 110592

__device__ __forceinline__ void gemm_core(
    const __half* __restrict__ A, const __half* __restrict__ W,
    const float* __restrict__ bias, float* __restrict__ Cf,
    __half* __restrict__ Ch, int mode)
{
    extern __shared__ __half hsmem[];
    const int M = MROWS, N = EMB, K = EMB;

    const int tid  = threadIdx.x;
    const int lane = tid & 31;
    const int warp = tid >> 5;
    const int bm = blockIdx.y * GBM;
    const int bn = blockIdx.x * GBN;

    const int wm = (warp >> 2) * 64;
    const int wn = (warp & 3) * 32;
    const int gid = lane >> 2;
    const int tig = lane & 3;

    // ldmatrix per-lane half offsets
    const int aoff = (wm + (lane & 15)) * PADH + (lane >> 4) * 8;
    const int boff = (wn + (lane & 7)) * PADH + (lane >> 3) * 8;

    float acc[4][4][4];
#pragma unroll
    for (int mt = 0; mt < 4; mt++)
#pragma unroll
        for (int nt = 0; nt < 4; nt++)
#pragma unroll
            for (int r = 0; r < 4; r++) acc[mt][nt][r] = 0.f;

    auto load_stage = [&](int s, int k0) {
        __half* As = hsmem + s * GSTG_HALFS;
        __half* Bs = As + GBM * PADH;
#pragma unroll
        for (int p = 0; p < 4; p++) {
            int idx = tid + p * 256;        // 0..1023
            int row = idx >> 3;             // 0..127
            int c   = (idx & 7) * 8;        // halfs 0..56
            CP_ASYNC16(smem_u32(As + row * PADH + c),
                       A + (size_t)(bm + row) * K + k0 + c);
            CP_ASYNC16(smem_u32(Bs + row * PADH + c),
                       W + (size_t)(bn + row) * K + k0 + c);
        }
        CP_COMMIT();
    };

    // one k32 half-chunk: 4 B-ldsm (n8 x k32 each), 2 x (4 A-ldsm + 16 mma)
    auto compute_half = [&](uint32_t abase, uint32_t bbase, int ks2) {
        uint32_t bfr[4][4];
#pragma unroll
        for (int nt = 0; nt < 4; nt++)
            LDSM_X4(bfr[nt], bbase + 2u * (boff + nt * 8 * PADH + ks2 * 32));
#pragma unroll
        for (int ksl = 0; ksl < 2; ksl++) {
            uint32_t afr[4][4];
#pragma unroll
            for (int mt = 0; mt < 4; mt++)
                LDSM_X4(afr[mt],
                        abase + 2u * (aoff + mt * 16 * PADH + ks2 * 32 + ksl * 16));
#pragma unroll
            for (int mt = 0; mt < 4; mt++)
#pragma unroll
                for (int nt = 0; nt < 4; nt++)
                    mma_f16(acc[mt][nt], afr[mt], &bfr[nt][ksl * 2]);
        }
    };

    const int nchunk = K / GBK;   // 16
    load_stage(0, 0);
    load_stage(1, GBK);

    for (int i = 0; i < nchunk; i++) {
        CP_WAIT(1);
        __syncthreads();
        // Ring safety: stage (i+2)%3 == (i-1)%3 fully read before all warps
        // passed the barrier above.
        const uint32_t abase = smem_u32(hsmem + (i % 3) * GSTG_HALFS);
        const uint32_t bbase = abase + GBM * PADH * 2;

        compute_half(abase, bbase, 0);
        if (i + 2 < nchunk) load_stage((i + 2) % 3, (i + 2) * GBK);
        compute_half(abase, bbase, 1);
    }

#pragma unroll
    for (int nt = 0; nt < 4; nt++) {
        const int c0 = bn + wn + nt * 8 + tig * 2;
        const float b0 = bias[c0], b1 = bias[c0 + 1];
#pragma unroll
        for (int mt = 0; mt < 4; mt++) {
            const int r0 = bm + wm + mt * 16 + gid;
            float2 v0 = make_float2(acc[mt][nt][0] + b0, acc[mt][nt][1] + b1);
            float2 v1 = make_float2(acc[mt][nt][2] + b0, acc[mt][nt][3] + b1);
            if (mode == 0) {
                *(float2*)(Cf + (size_t)r0 * N + c0) = v0;
                *(float2*)(Cf + (size_t)(r0 + 8) * N + c0) = v1;
            } else if (mode == 1) {
                *(__half2*)(Ch + (size_t)r0 * N + c0) = __floats2half2_rn(v0.x, v0.y);
                *(__half2*)(Ch + (size_t)(r0 + 8) * N + c0) = __floats2half2_rn(v1.x, v1.y);
            } else {   // transposed: C[col][row], ldc = M
                Ch[(size_t)c0 * M + r0]           = __float2half_rn(v0.x);
                Ch[(size_t)(c0 + 1) * M + r0]     = __float2half_rn(v0.y);
                Ch[(size_t)c0 * M + r0 + 8]       = __float2half_rn(v1.x);
                Ch[(size_t)(c0 + 1) * M + r0 + 8] = __float2half_rn(v1.y);
            }
        }
    }
}

// Fused Q/K/V projection: blockIdx.z selects tensor.
__global__ __launch_bounds__(256, 2) void gemm_qkv(
    const float* __restrict__ bq, const float* __restrict__ bk,
    const float* __restrict__ bv)
{
    switch (blockIdx.z) {
        case 0: gemm_core(g_QR, g_WQ, bq, nullptr, g_Q, 1); break;
        case 1: gemm_core(g_KR, g_WK, bk, nullptr, g_K, 1); break;
        default: gemm_core(g_VR, g_WV, bv, nullptr, g_VT, 2); break;
    }
}

// Output projection (fp32 out).
__global__ __launch_bounds__(256, 2) void gemm_out(
    const float* __restrict__ bo, float* __restrict__ out)
{
    gemm_core(g_A, g_WO, bo, out, nullptr, 0);
}

// ---------------------------------------------------------------------------
// Flash attention, mma.sync fp16 (fp32 accum): ldmatrix + transposed V.
// CTA: 128 q rows, 128 threads, 4 warps (32 q rows each, mt=2).
// KV slot: K rows [0,64) key-major halfs; V^T rows [64,128) hd-major halfs.
// ---------------------------------------------------------------------------
#define AQ   128
#define AKV  64
#define APADH 72
#define AREG_HALFS (AQ * APADH)                 // 9216 halfs per region
#define ATTN_SMEM_BYTES (3 * AREG_HALFS * 2)    // 55296

__global__ __launch_bounds__(128, 2) void flash_attn_mma()
{
    extern __shared__ __half hdsm[];
    __half* R0 = hdsm;                     // Q staging -> KV slot for odd tiles
    __half* R1 = hdsm + AREG_HALFS;        // KV slot for even tiles
    __half* PsBase = hdsm + 2 * AREG_HALFS;

    const int qt = blockIdx.x;
    const int h  = blockIdx.y;
    const int b  = blockIdx.z;

    const __half* Qb = g_Q + ((size_t)b * SEQ + qt * AQ) * EMB + h * HDIM;
    const __half* Kb = g_K + (size_t)b * SEQ * EMB + h * HDIM;
    const __half* Vtb = g_VT + (size_t)(h * HDIM) * MROWS + (size_t)b * SEQ;
    __half*       Ob = g_A + ((size_t)b * SEQ + qt * AQ) * EMB + h * HDIM;

    const int tid  = threadIdx.x;
    const int lane = tid & 31;
    const int warp = tid >> 5;
    const int gid  = lane >> 2;
    const int tig  = lane & 3;
    const int wm   = warp * 32;

    // ldmatrix per-lane half offsets
    const int aoff = (wm + (lane & 15)) * APADH + (lane >> 4) * 8;   // A rows (q)
    const int boff = (lane & 7) * APADH + (lane >> 3) * 8;           // B rows

    // K rows [0,64) at slot; V^T rows [64,128) (hd-major).
    auto load_kv = [&](__half* base, int kt) {
        const __half* Kt = Kb + (size_t)kt * AKV * EMB;
        const __half* Vt = Vtb + (size_t)kt * AKV;
#pragma unroll
        for (int p = 0; p < 4; p++) {
            int idx = tid + p * 128;       // 0..511
            int row = idx >> 3;            // 0..63
            int c   = (idx & 7) * 8;       // halfs
            CP_ASYNC16(smem_u32(base + row * APADH + c),
                       Kt + (size_t)row * EMB + c);
            CP_ASYNC16(smem_u32(base + (AKV + row) * APADH + c),
                       Vt + (size_t)row * MROWS + c);
        }
        CP_COMMIT();
    };

    // Prologue: Q -> R0 (async), KV0 -> R1 (async).
#pragma unroll
    for (int p = 0; p < 8; p++) {
        int idx = tid + p * 128;           // 0..1023
        int row = idx >> 3;                // 0..127
        int c   = (idx & 7) * 8;
        CP_ASYNC16(smem_u32(R0 + row * APADH + c),
                   Qb + (size_t)row * EMB + c);
    }
    CP_COMMIT();
    load_kv(R1, 0);

    CP_WAIT(1);
    __syncthreads();

    // Hoist Q fragments via ldmatrix; scale by softmax*log2e in fp32, repack.
    const float qscale = 0.125f * 1.4426950408889634f;
    const uint32_t r0base = smem_u32(R0);
    uint32_t qfr[2][4][4];
#pragma unroll
    for (int mt = 0; mt < 2; mt++)
#pragma unroll
        for (int ks = 0; ks < 4; ks++) {
            uint32_t t[4];
            LDSM_X4(t, r0base + 2u * (aoff + mt * 16 * APADH + ks * 16));
#pragma unroll
            for (int j = 0; j < 4; j++) {
                float2 f = __half22float2(*(__half2*)&t[j]);
                __half2 hh = __floats2half2_rn(f.x * qscale, f.y * qscale);
                qfr[mt][ks][j] = *(uint32_t*)&hh;
            }
        }
    __syncthreads();
    load_kv(R0, 1);

    float oacc[2][8][4];
#pragma unroll
    for (int mt = 0; mt < 2; mt++)
#pragma unroll
        for (int nt = 0; nt < 8; nt++)
#pragma unroll
            for (int r = 0; r < 4; r++) oacc[mt][nt][r] = 0.f;
    float mrow[2][2], lrow[2][2];
#pragma unroll
    for (int mt = 0; mt < 2; mt++) {
        mrow[mt][0] = -1e30f; mrow[mt][1] = -1e30f;
        lrow[mt][0] = 0.f;    lrow[mt][1] = 0.f;
    }

    const uint32_t psbase = smem_u32(PsBase);
    const int ntile = SEQ / AKV;   // 32
    for (int kt = 0; kt < ntile; kt++) {
        CP_WAIT(1);
        __syncthreads();

        __half* slot = (kt & 1) ? R0 : R1;
        const uint32_t kbase = smem_u32(slot);
        const uint32_t vbase = kbase + AKV * APADH * 2;

        // S = Q K^T (k = hd = 64 -> 2 x k32).
        float sacc[2][8][4];
#pragma unroll
        for (int mt = 0; mt < 2; mt++)
#pragma unroll
            for (int nt = 0; nt < 8; nt++)
#pragma unroll
                for (int r = 0; r < 4; r++) sacc[mt][nt][r] = 0.f;

#pragma unroll
        for (int ks2 = 0; ks2 < 2; ks2++) {
#pragma unroll
            for (int nt = 0; nt < 8; nt++) {
                uint32_t bf[4];
                LDSM_X4(bf, kbase + 2u * (boff + nt * 8 * APADH + ks2 * 32));
                mma_f16(sacc[0][nt], qfr[0][ks2 * 2], bf);
                mma_f16(sacc[1][nt], qfr[1][ks2 * 2], bf);
                mma_f16(sacc[0][nt], qfr[0][ks2 * 2 + 1], bf + 2);
                mma_f16(sacc[1][nt], qfr[1][ks2 * 2 + 1], bf + 2);
            }
        }

        // Online softmax (exp2 domain, fp32).
#pragma unroll
        for (int mt = 0; mt < 2; mt++) {
            float mx0 = -1e30f, mx1 = -1e30f;
#pragma unroll
            for (int nt = 0; nt < 8; nt++) {
                mx0 = fmaxf(mx0, fmaxf(sacc[mt][nt][0], sacc[mt][nt][1]));
                mx1 = fmaxf(mx1, fmaxf(sacc[mt][nt][2], sacc[mt][nt][3]));
            }
            mx0 = fmaxf(mx0, __shfl_xor_sync(0xffffffffu, mx0, 1));
            mx0 = fmaxf(mx0, __shfl_xor_sync(0xffffffffu, mx0, 2));
            mx1 = fmaxf(mx1, __shfl_xor_sync(0xffffffffu, mx1, 1));
            mx1 = fmaxf(mx1, __shfl_xor_sync(0xffffffffu, mx1, 2));

            float mn0 = fmaxf(mrow[mt][0], mx0), mn1 = fmaxf(mrow[mt][1], mx1);
            float corr0 = fexp2(mrow[mt][0] - mn0), corr1 = fexp2(mrow[mt][1] - mn1);
            float s0 = 0.f, s1 = 0.f;
#pragma unroll
            for (int nt = 0; nt < 8; nt++) {
                sacc[mt][nt][0] = fexp2(sacc[mt][nt][0] - mn0);
                sacc[mt][nt][1] = fexp2(sacc[mt][nt][1] - mn0);
                sacc[mt][nt][2] = fexp2(sacc[mt][nt][2] - mn1);
                sacc[mt][nt][3] = fexp2(sacc[mt][nt][3] - mn1);
                s0 += sacc[mt][nt][0] + sacc[mt][nt][1];
                s1 += sacc[mt][nt][2] + sacc[mt][nt][3];
            }
            s0 += __shfl_xor_sync(0xffffffffu, s0, 1);
            s0 += __shfl_xor_sync(0xffffffffu, s0, 2);
            s1 += __shfl_xor_sync(0xffffffffu, s1, 1);
            s1 += __shfl_xor_sync(0xffffffffu, s1, 2);
            lrow[mt][0] = lrow[mt][0] * corr0 + s0;  mrow[mt][0] = mn0;
            lrow[mt][1] = lrow[mt][1] * corr1 + s1;  mrow[mt][1] = mn1;
#pragma unroll
            for (int nt = 0; nt < 8; nt++) {
                oacc[mt][nt][0] *= corr0; oacc[mt][nt][1] *= corr0;
                oacc[mt][nt][2] *= corr1; oacc[mt][nt][3] *= corr1;
            }

            // Stage P as packed fp16 into this warp's private rows of Ps.
#pragma unroll
            for (int nt = 0; nt < 8; nt++) {
                __half2 h0 = __floats2half2_rn(sacc[mt][nt][0], sacc[mt][nt][1]);
                __half2 h1 = __floats2half2_rn(sacc[mt][nt][2], sacc[mt][nt][3]);
                *(__half2*)(PsBase + (wm + mt * 16 + gid) * APADH + nt * 8 + tig * 2) = h0;
                *(__half2*)(PsBase + (wm + mt * 16 + gid + 8) * APADH + nt * 8 + tig * 2) = h1;
            }
        }
        __syncwarp();

        // O += P V : A = Ps (half), B = V^T (hd-major half), both via ldmatrix.
#pragma unroll
        for (int ks2 = 0; ks2 < 2; ks2++) {
            uint32_t pa[2][2][4];
#pragma unroll
            for (int mt = 0; mt < 2; mt++)
#pragma unroll
                for (int ksl = 0; ksl < 2; ksl++)
                    LDSM_X4(pa[mt][ksl],
                            psbase + 2u * (aoff + mt * 16 * APADH + ks2 * 32 + ksl * 16));
#pragma unroll
            for (int nt = 0; nt < 8; nt++) {
                uint32_t vf[4];
                LDSM_X4(vf, vbase + 2u * (boff + nt * 8 * APADH + ks2 * 32));
                mma_f16(oacc[0][nt], pa[0][0], vf);
                mma_f16(oacc[1][nt], pa[1][0], vf);
                mma_f16(oacc[0][nt], pa[0][1], vf + 2);
                mma_f16(oacc[1][nt], pa[1][1], vf + 2);
            }
        }

        __syncthreads();
        if (kt + 2 < ntile) load_kv(slot, kt + 2);
    }

    // Epilogue: normalize, round to fp16 (feeds final GEMM), write.
#pragma unroll
    for (int mt = 0; mt < 2; mt++) {
        const float inv0 = 1.0f / lrow[mt][0], inv1 = 1.0f / lrow[mt][1];
        const int r0 = wm + mt * 16 + gid, r1 = r0 + 8;
#pragma unroll
        for (int nt = 0; nt < 8; nt++) {
            const int c = nt * 8 + tig * 2;
            *(__half2*)(Ob + (size_t)r0 * EMB + c) =
                __floats2half2_rn(oacc[mt][nt][0] * inv0, oacc[mt][nt][1] * inv0);
            *(__half2*)(Ob + (size_t)r1 * EMB + c) =
                __floats2half2_rn(oacc[mt][nt][2] * inv1, oacc[mt][nt][3] * inv1);
        }
    }
}

// ---------------------------------------------------------------------------
// Launch
// ---------------------------------------------------------------------------
extern "C" void kernel_launch(void* const* d_in, const int* in_sizes, int n_in,
                              void* d_out, int out_size)
{
    const float* query = (const float*)d_in[0];
    const float* key   = (const float*)d_in[1];
    const float* value = (const float*)d_in[2];
    const float* bq    = (const float*)d_in[4];
    const float* bk    = (const float*)d_in[6];
    const float* bv    = (const float*)d_in[8];
    const float* bo    = (const float*)d_in[10];
    float* out = (float*)d_out;

    cudaFuncSetAttribute(gemm_qkv,
                         cudaFuncAttributeMaxDynamicSharedMemorySize,
                         GEMM_SMEM_BYTES);
    cudaFuncSetAttribute(gemm_out,
                         cudaFuncAttributeMaxDynamicSharedMemorySize,
                         GEMM_SMEM_BYTES);
    cudaFuncSetAttribute(flash_attn_mma,
                         cudaFuncAttributeMaxDynamicSharedMemorySize,
                         ATTN_SMEM_BYTES);

    // Prologue: fp16-round inputs + weights into scratch.
    round_f16_all<<<dim3(512, 7), 256>>>(
        query, key, value,
        (const float*)d_in[3], (const float*)d_in[5],
        (const float*)d_in[7], (const float*)d_in[9]);

    dim3 gqkv(EMB / GBN, MROWS / GBM, 3);   // (8, 32, 3)
    gemm_qkv<<<gqkv, 256, GEMM_SMEM_BYTES>>>(bq, bk, bv);

    dim3 gattn(SEQ / AQ, NHEAD, BATCH);  // (16, 16, 2)
    flash_attn_mma<<<gattn, 128, ATTN_SMEM_BYTES>>>();

    dim3 gout(EMB / GBN, MROWS / GBM);   // (8, 32)
    gemm_out<<<gout, 256, GEMM_SMEM_BYTES>>>(bo, out);
}